// round 1
// baseline (speedup 1.0000x reference)
#include <cuda_runtime.h>
#include <math.h>
#include <cstdint>

// ---------------- scratch (static device globals; no allocations) ----------
__device__ float g_y[16777216];      // [8,512,4096]   y = w0@x + b0
__device__ float g_qkvp[50331648];   // [8,1536,4096]  pre-depthwise qkv
__device__ float g_qkv[50331648];    // [8,1536,4096]  post-depthwise qkv
__device__ float g_g1[8388608];      // [8,256,4096]   relu(wg1@y + bg1)
__device__ float g_partial[128];
__device__ float g_qinv[4096];       // [b*512 + h*64 + c]
__device__ float g_kinv[4096];
__device__ int   g_dk;

// ---------------- generic batched SGEMM: C[b] = A @ B[b] (+bias)(relu) -----
// A: [M,K] row-major (shared over batch), B: [K,N] row-major, C: [M,N]
template<bool RELU, bool BIAS>
__global__ void __launch_bounds__(256) sgemm128(
    const float* __restrict__ A, const float* __restrict__ Bm,
    const float* __restrict__ bias, float* __restrict__ C,
    int M, int N, int K, size_t sB, size_t sC)
{
    constexpr int BM = 128, BN = 128, BK = 16, TM = 8, TN = 8;
    __shared__ float As[BK][BM];
    __shared__ float Bs[BK][BN];

    const float* Bb = Bm + (size_t)blockIdx.z * sB;
    float*       Cb = C  + (size_t)blockIdx.z * sC;
    const int bm = blockIdx.y * BM;
    const int bn = blockIdx.x * BN;
    const int tid = threadIdx.x;
    const int tx = tid & 15;
    const int ty = tid >> 4;

    float acc[TM][TN];
    #pragma unroll
    for (int i = 0; i < TM; i++)
        #pragma unroll
        for (int j = 0; j < TN; j++) acc[i][j] = 0.f;

    for (int k0 = 0; k0 < K; k0 += BK) {
        // load A tile (BMxBK), store transposed into As[k][m]
        #pragma unroll
        for (int l = 0; l < 2; l++) {
            int f   = tid + l * 256;          // float4 index, 512 total
            int row = f >> 2;                 // m within tile
            int c4  = (f & 3) * 4;            // k within tile
            float4 v = *reinterpret_cast<const float4*>(
                A + (size_t)(bm + row) * K + k0 + c4);
            As[c4 + 0][row] = v.x; As[c4 + 1][row] = v.y;
            As[c4 + 2][row] = v.z; As[c4 + 3][row] = v.w;
        }
        // load B tile (BKxBN) directly
        #pragma unroll
        for (int l = 0; l < 2; l++) {
            int f   = tid + l * 256;
            int row = f >> 5;
            int c4  = (f & 31) * 4;
            *reinterpret_cast<float4*>(&Bs[row][c4]) =
                *reinterpret_cast<const float4*>(
                    Bb + (size_t)(k0 + row) * N + bn + c4);
        }
        __syncthreads();
        #pragma unroll
        for (int kk = 0; kk < BK; kk++) {
            float4 a0 = *reinterpret_cast<const float4*>(&As[kk][ty * TM]);
            float4 a1 = *reinterpret_cast<const float4*>(&As[kk][ty * TM + 4]);
            float4 b0 = *reinterpret_cast<const float4*>(&Bs[kk][tx * TN]);
            float4 b1 = *reinterpret_cast<const float4*>(&Bs[kk][tx * TN + 4]);
            float ar[8] = {a0.x, a0.y, a0.z, a0.w, a1.x, a1.y, a1.z, a1.w};
            float br[8] = {b0.x, b0.y, b0.z, b0.w, b1.x, b1.y, b1.z, b1.w};
            #pragma unroll
            for (int i = 0; i < TM; i++)
                #pragma unroll
                for (int j = 0; j < TN; j++)
                    acc[i][j] = fmaf(ar[i], br[j], acc[i][j]);
        }
        __syncthreads();
    }

    #pragma unroll
    for (int i = 0; i < TM; i++) {
        int m = bm + ty * TM + i;
        float bv = BIAS ? bias[m] : 0.f;
        #pragma unroll
        for (int j = 0; j < TN; j += 4) {
            float4 v;
            v.x = acc[i][j + 0] + bv; v.y = acc[i][j + 1] + bv;
            v.z = acc[i][j + 2] + bv; v.w = acc[i][j + 3] + bv;
            if (RELU) {
                v.x = fmaxf(v.x, 0.f); v.y = fmaxf(v.y, 0.f);
                v.z = fmaxf(v.z, 0.f); v.w = fmaxf(v.w, 0.f);
            }
            *reinterpret_cast<float4*>(Cb + (size_t)m * N + bn + tx * TN + j) = v;
        }
    }
}

// ---------------- depthwise 3x3, SAME, groups = channels -------------------
__global__ void __launch_bounds__(256) dwconv_kernel(
    const float* __restrict__ inp, const float* __restrict__ w,
    float* __restrict__ outp)
{
    const int bc = blockIdx.x;          // b*1536 + ch
    const int ch = bc % 1536;
    const float* ip = inp + (size_t)bc * 4096;
    float*       op = outp + (size_t)bc * 4096;
    __shared__ float sh[66 * 66];
    const int tid = threadIdx.x;
    for (int i = tid; i < 66 * 66; i += 256) {
        int r = i / 66 - 1;
        int c = i % 66 - 1;
        sh[i] = (r >= 0 && r < 64 && c >= 0 && c < 64) ? ip[r * 64 + c] : 0.f;
    }
    const float* wp = w + (size_t)ch * 9;
    float w0 = wp[0], w1 = wp[1], w2 = wp[2];
    float w3 = wp[3], w4 = wp[4], w5 = wp[5];
    float w6 = wp[6], w7 = wp[7], w8 = wp[8];
    __syncthreads();
    #pragma unroll
    for (int j = 0; j < 16; j++) {
        int p = tid + j * 256;
        int y = p >> 6, x = p & 63;
        const float* s0 = &sh[y * 66 + x];
        float acc = s0[0]   * w0 + s0[1]   * w1 + s0[2]   * w2
                  + s0[66]  * w3 + s0[67]  * w4 + s0[68]  * w5
                  + s0[132] * w6 + s0[133] * w7 + s0[134] * w8;
        op[p] = acc;
    }
}

// ---------------- gate: per-pixel sigmoid(dot(g1, wg2)+bg2), partial sums --
__global__ void __launch_bounds__(256) gate_dot(
    const float* __restrict__ g1, const float* __restrict__ wg2,
    const float* __restrict__ bg2)
{
    __shared__ float ws[256];
    __shared__ float red[256];
    const int tid = threadIdx.x;
    ws[tid] = wg2[tid];
    __syncthreads();
    const int P = blockIdx.x * 256 + tid;   // pixel id in [0, 32768)
    const int b = P >> 12;
    const int p = P & 4095;
    const float* base = g1 + (size_t)b * 256 * 4096 + p;
    float acc = bg2[0];
    #pragma unroll 8
    for (int ch = 0; ch < 256; ch++)
        acc = fmaf(base[(size_t)ch * 4096], ws[ch], acc);
    float s = 1.f / (1.f + expf(-acc));
    red[tid] = s;
    __syncthreads();
    for (int st = 128; st > 0; st >>= 1) {
        if (tid < st) red[tid] += red[tid + st];
        __syncthreads();
    }
    if (tid == 0) g_partial[blockIdx.x] = red[0];
}

__global__ void gate_fin()
{
    if (threadIdx.x == 0 && blockIdx.x == 0) {
        float t = 0.f;
        for (int i = 0; i < 128; i++) t += g_partial[i];
        float mean = t * (1.f / 32768.f);
        int k = (int)floorf(64.f * mean);
        k = max(0, min(64, k));
        g_dk = k;
    }
}

// ---------------- row L2 inverse norms for q and k --------------------------
__global__ void __launch_bounds__(256) norm_kernel(const float* __restrict__ qkv)
{
    const int r  = blockIdx.x;           // 0..8191
    const int qk = r >> 12;              // 0 = q, 1 = k
    const int rr = r & 4095;             // b*512 + hc
    const int b  = rr >> 9;
    const int hc = rr & 511;
    const float* p = qkv + ((size_t)b * 1536 + (size_t)qk * 512 + hc) * 4096;
    const int tid = threadIdx.x;
    float s = 0.f;
    for (int i = tid * 4; i < 4096; i += 1024) {
        float4 v = *reinterpret_cast<const float4*>(p + i);
        s += v.x * v.x + v.y * v.y + v.z * v.z + v.w * v.w;
    }
    __shared__ float red[256];
    red[tid] = s;
    __syncthreads();
    for (int st = 128; st > 0; st >>= 1) {
        if (tid < st) red[tid] += red[tid + st];
        __syncthreads();
    }
    if (tid == 0) {
        float inv = 1.f / fmaxf(sqrtf(red[0]), 1e-12f);
        (qk ? g_kinv : g_qinv)[rr] = inv;
    }
}

// ---------------- fused channel attention per (b,h) ------------------------
// S = QK^T (K=4096), scale by qinv*kinv*temp, top-dynamic_k + softmax,
// out = (a1+a2+a3+a4) * S @ V
__global__ void __launch_bounds__(256) attn_kernel(
    const float* __restrict__ qkv, const float* __restrict__ temp,
    const float* __restrict__ a1p, const float* __restrict__ a2p,
    const float* __restrict__ a3p, const float* __restrict__ a4p,
    float* __restrict__ outp)
{
    __shared__ float Qt[64 * 68];   // phase1: Q tile (n x c); phase2+: S (c x d)
    __shared__ float Kt[64 * 68];   // phase1: K tile (n x c); phase3: V (d x n)

    const int bh = blockIdx.x;
    const int b = bh >> 3, h = bh & 7;
    const float* Qg = qkv + ((size_t)b * 1536 + (size_t)h * 64) * 4096;
    const float* Kg = Qg + (size_t)512 * 4096;
    const float* Vg = Qg + (size_t)1024 * 4096;
    float* Og = outp + ((size_t)b * 512 + (size_t)h * 64) * 4096;

    const int tid = threadIdx.x;
    const int tx = tid & 15, ty = tid >> 4;

    // ---- phase 1: S = Q K^T over n = 4096 ----
    float acc[4][4];
    #pragma unroll
    for (int i = 0; i < 4; i++)
        #pragma unroll
        for (int j = 0; j < 4; j++) acc[i][j] = 0.f;

    for (int n0 = 0; n0 < 4096; n0 += 64) {
        #pragma unroll
        for (int l = 0; l < 4; l++) {
            int f   = tid + l * 256;
            int row = f >> 4;           // c (0..63)
            int nl  = (f & 15) * 4;     // n within tile
            float4 q4 = *reinterpret_cast<const float4*>(
                Qg + (size_t)row * 4096 + n0 + nl);
            float4 k4 = *reinterpret_cast<const float4*>(
                Kg + (size_t)row * 4096 + n0 + nl);
            Qt[(nl + 0) * 68 + row] = q4.x; Qt[(nl + 1) * 68 + row] = q4.y;
            Qt[(nl + 2) * 68 + row] = q4.z; Qt[(nl + 3) * 68 + row] = q4.w;
            Kt[(nl + 0) * 68 + row] = k4.x; Kt[(nl + 1) * 68 + row] = k4.y;
            Kt[(nl + 2) * 68 + row] = k4.z; Kt[(nl + 3) * 68 + row] = k4.w;
        }
        __syncthreads();
        #pragma unroll 8
        for (int nn = 0; nn < 64; nn++) {
            float4 av = *reinterpret_cast<const float4*>(&Qt[nn * 68 + ty * 4]);
            float4 bv = *reinterpret_cast<const float4*>(&Kt[nn * 68 + tx * 4]);
            float ar[4] = {av.x, av.y, av.z, av.w};
            float br[4] = {bv.x, bv.y, bv.z, bv.w};
            #pragma unroll
            for (int i = 0; i < 4; i++)
                #pragma unroll
                for (int j = 0; j < 4; j++)
                    acc[i][j] = fmaf(ar[i], br[j], acc[i][j]);
        }
        __syncthreads();
    }

    // ---- scale by inverse norms * temperature, store S into Qt[c*68+d] ----
    const int base = b * 512 + h * 64;
    const float tmp = temp[h];
    #pragma unroll
    for (int i = 0; i < 4; i++) {
        float qi = g_qinv[base + ty * 4 + i] * tmp;
        #pragma unroll
        for (int j = 0; j < 4; j++)
            Qt[(ty * 4 + i) * 68 + (tx * 4 + j)] =
                acc[i][j] * qi * g_kinv[base + tx * 4 + j];
    }
    __syncthreads();

    // ---- phase 2: top-dynamic_k (stable ties) + softmax, per row ----
    const int kd = g_dk;
    if (tid < 64) {
        float* row = &Qt[tid * 68];
        float m = -INFINITY;
        unsigned long long keep = 0ull;
        for (int i = 0; i < 64; i++) {
            float ai = row[i];
            int cnt = 0;
            for (int j = 0; j < 64; j++) {
                float aj = row[j];
                cnt += (aj > ai) ? 1 : ((aj == ai && j < i) ? 1 : 0);
            }
            if (cnt < kd) { keep |= (1ull << i); m = fmaxf(m, ai); }
        }
        float s = 0.f;
        for (int i = 0; i < 64; i++) {
            float e = ((keep >> i) & 1ull) ? expf(row[i] - m) : 0.f;
            row[i] = e;
            s += e;
        }
        float inv = (s > 0.f) ? 1.f / s : 0.f;
        for (int i = 0; i < 64; i++) row[i] *= inv;
    }
    __syncthreads();

    // ---- phase 3: out = sc * S @ V ----
    const float sc = a1p[0] + a2p[0] + a3p[0] + a4p[0];
    for (int n0 = 0; n0 < 4096; n0 += 64) {
        #pragma unroll
        for (int l = 0; l < 4; l++) {
            int f   = tid + l * 256;
            int row = f >> 4;           // d
            int nl  = (f & 15) * 4;
            *reinterpret_cast<float4*>(&Kt[row * 68 + nl]) =
                *reinterpret_cast<const float4*>(
                    Vg + (size_t)row * 4096 + n0 + nl);
        }
        __syncthreads();
        float o[4][4];
        #pragma unroll
        for (int i = 0; i < 4; i++)
            #pragma unroll
            for (int j = 0; j < 4; j++) o[i][j] = 0.f;
        #pragma unroll 4
        for (int d = 0; d < 64; d++) {
            float s0 = Qt[(ty * 4 + 0) * 68 + d];
            float s1 = Qt[(ty * 4 + 1) * 68 + d];
            float s2 = Qt[(ty * 4 + 2) * 68 + d];
            float s3 = Qt[(ty * 4 + 3) * 68 + d];
            float4 v4 = *reinterpret_cast<const float4*>(&Kt[d * 68 + tx * 4]);
            o[0][0] = fmaf(s0, v4.x, o[0][0]); o[0][1] = fmaf(s0, v4.y, o[0][1]);
            o[0][2] = fmaf(s0, v4.z, o[0][2]); o[0][3] = fmaf(s0, v4.w, o[0][3]);
            o[1][0] = fmaf(s1, v4.x, o[1][0]); o[1][1] = fmaf(s1, v4.y, o[1][1]);
            o[1][2] = fmaf(s1, v4.z, o[1][2]); o[1][3] = fmaf(s1, v4.w, o[1][3]);
            o[2][0] = fmaf(s2, v4.x, o[2][0]); o[2][1] = fmaf(s2, v4.y, o[2][1]);
            o[2][2] = fmaf(s2, v4.z, o[2][2]); o[2][3] = fmaf(s2, v4.w, o[2][3]);
            o[3][0] = fmaf(s3, v4.x, o[3][0]); o[3][1] = fmaf(s3, v4.y, o[3][1]);
            o[3][2] = fmaf(s3, v4.z, o[3][2]); o[3][3] = fmaf(s3, v4.w, o[3][3]);
        }
        #pragma unroll
        for (int i = 0; i < 4; i++) {
            float4 w;
            w.x = o[i][0] * sc; w.y = o[i][1] * sc;
            w.z = o[i][2] * sc; w.w = o[i][3] * sc;
            *reinterpret_cast<float4*>(
                Og + (size_t)(ty * 4 + i) * 4096 + n0 + tx * 4) = w;
        }
        __syncthreads();
    }
}

// ---------------------------------------------------------------------------
extern "C" void kernel_launch(void* const* d_in, const int* in_sizes, int n_in,
                              void* d_out, int out_size)
{
    const float* x    = (const float*)d_in[0];
    const float* w0   = (const float*)d_in[1];
    const float* b0   = (const float*)d_in[2];
    const float* wqkv = (const float*)d_in[3];
    const float* wdw  = (const float*)d_in[4];
    const float* temp = (const float*)d_in[5];
    const float* wg1  = (const float*)d_in[6];
    const float* bg1  = (const float*)d_in[7];
    const float* wg2  = (const float*)d_in[8];
    const float* bg2  = (const float*)d_in[9];
    const float* a1   = (const float*)d_in[10];
    const float* a2   = (const float*)d_in[11];
    const float* a3   = (const float*)d_in[12];
    const float* a4   = (const float*)d_in[13];
    float* out = (float*)d_out;

    float *y, *qkvp, *qkvb, *g1;
    cudaGetSymbolAddress((void**)&y,    g_y);
    cudaGetSymbolAddress((void**)&qkvp, g_qkvp);
    cudaGetSymbolAddress((void**)&qkvb, g_qkv);
    cudaGetSymbolAddress((void**)&g1,   g_g1);

    dim3 blk(256);

    // y = w0 @ x + b0                   [512,512] x [512,4096] per batch
    sgemm128<false, true><<<dim3(32, 4, 8), blk>>>(
        w0, x, b0, y, 512, 4096, 512,
        (size_t)512 * 4096, (size_t)512 * 4096);

    // qkv_pre = wqkv @ y                [1536,512] x [512,4096] per batch
    sgemm128<false, false><<<dim3(32, 12, 8), blk>>>(
        wqkv, y, nullptr, qkvp, 1536, 4096, 512,
        (size_t)512 * 4096, (size_t)1536 * 4096);

    // depthwise 3x3 SAME
    dwconv_kernel<<<8 * 1536, blk>>>(qkvp, wdw, qkvb);

    // g1 = relu(wg1 @ y + bg1)          [256,512] x [512,4096] per batch
    sgemm128<true, true><<<dim3(32, 2, 8), blk>>>(
        wg1, y, bg1, g1, 256, 4096, 512,
        (size_t)512 * 4096, (size_t)256 * 4096);

    // dynamic_k = floor(64 * mean(sigmoid(g1 . wg2 + bg2)))
    gate_dot<<<128, blk>>>(g1, wg2, bg2);
    gate_fin<<<1, 32>>>();

    // inverse L2 norms of q and k rows
    norm_kernel<<<8192, blk>>>(qkvb);

    // fused channel attention + output
    attn_kernel<<<64, blk>>>(qkvb, temp, a1, a2, a3, a4, out);
}

// round 2
// speedup vs baseline: 1.2839x; 1.2839x over previous
#include <cuda_runtime.h>
#include <math.h>
#include <cstdint>

// ---------------- scratch (static device globals; no allocations) ----------
__device__ float g_Wqkv[786432];     // [1536,512]  wqkv@w0
__device__ float g_Wg1[131072];      // [256,512]   wg1@w0
__device__ float g_bqkv[1536];
__device__ float g_bg1[256];
__device__ float g_qkvp[50331648];   // [8,1536,4096]  pre-depthwise qkv
__device__ float g_qkv[50331648];    // [8,1536,4096]  post-depthwise qkv
__device__ float g_g1[8388608];      // [8,256,4096]   relu(Wg1'@x + bg1')
__device__ float g_partial[128];
__device__ float g_qinv[4096];       // [b*512 + h*64 + c]
__device__ float g_kinv[4096];
__device__ float g_Spart[2097152];   // [8 chunk][64 bh][64][64] partial QK^T
__device__ float g_P[262144];        // [64 bh][64][64] softmax probs
__device__ int   g_dk;

// ---------------- double-buffered SGEMM: C[b] = A @ B[b] (+bias)(relu) -----
// A: [M,K] row-major (shared over batch), B: [K,N] row-major, C: [M,N]
template<bool RELU, bool BIAS>
__global__ void __launch_bounds__(256) sgemm_db(
    const float* __restrict__ A, const float* __restrict__ Bm,
    const float* __restrict__ bias, float* __restrict__ C,
    int M, int N, int K, size_t sB, size_t sC)
{
    constexpr int BM = 128, BN = 128, BK = 16;
    __shared__ float As[2][BK][BM];
    __shared__ float Bs[2][BK][BN];

    const float* Bb = Bm + (size_t)blockIdx.z * sB;
    float*       Cb = C  + (size_t)blockIdx.z * sC;
    const int bm = blockIdx.y * BM;
    const int bn = blockIdx.x * BN;
    const int tid = threadIdx.x;
    const int tx = tid & 15;
    const int ty = tid >> 4;

    const int arow = tid >> 2;         // 0..63 (+64 for second load)
    const int ac4  = (tid & 3) * 4;    // k offset within tile
    const int brow = tid >> 5;         // 0..7  (+8 for second load)
    const int bc4  = (tid & 31) * 4;   // n offset within tile

    float4 ra0, ra1, rb0, rb1;

    // prologue load k0 = 0
    ra0 = *reinterpret_cast<const float4*>(A + (size_t)(bm + arow) * K + ac4);
    ra1 = *reinterpret_cast<const float4*>(A + (size_t)(bm + arow + 64) * K + ac4);
    rb0 = *reinterpret_cast<const float4*>(Bb + (size_t)(brow) * N + bn + bc4);
    rb1 = *reinterpret_cast<const float4*>(Bb + (size_t)(brow + 8) * N + bn + bc4);
    As[0][ac4 + 0][arow] = ra0.x; As[0][ac4 + 1][arow] = ra0.y;
    As[0][ac4 + 2][arow] = ra0.z; As[0][ac4 + 3][arow] = ra0.w;
    As[0][ac4 + 0][arow + 64] = ra1.x; As[0][ac4 + 1][arow + 64] = ra1.y;
    As[0][ac4 + 2][arow + 64] = ra1.z; As[0][ac4 + 3][arow + 64] = ra1.w;
    *reinterpret_cast<float4*>(&Bs[0][brow][bc4]) = rb0;
    *reinterpret_cast<float4*>(&Bs[0][brow + 8][bc4]) = rb1;
    __syncthreads();

    float acc[8][8] = {};
    int buf = 0;

    for (int k0 = 0; k0 < K; k0 += BK) {
        const bool more = (k0 + BK) < K;
        if (more) {
            int kn = k0 + BK;
            ra0 = *reinterpret_cast<const float4*>(A + (size_t)(bm + arow) * K + kn + ac4);
            ra1 = *reinterpret_cast<const float4*>(A + (size_t)(bm + arow + 64) * K + kn + ac4);
            rb0 = *reinterpret_cast<const float4*>(Bb + (size_t)(kn + brow) * N + bn + bc4);
            rb1 = *reinterpret_cast<const float4*>(Bb + (size_t)(kn + brow + 8) * N + bn + bc4);
        }
        #pragma unroll
        for (int kk = 0; kk < BK; kk++) {
            float4 a0 = *reinterpret_cast<const float4*>(&As[buf][kk][ty * 8]);
            float4 a1 = *reinterpret_cast<const float4*>(&As[buf][kk][ty * 8 + 4]);
            float4 b0 = *reinterpret_cast<const float4*>(&Bs[buf][kk][tx * 8]);
            float4 b1 = *reinterpret_cast<const float4*>(&Bs[buf][kk][tx * 8 + 4]);
            float ar[8] = {a0.x, a0.y, a0.z, a0.w, a1.x, a1.y, a1.z, a1.w};
            float br[8] = {b0.x, b0.y, b0.z, b0.w, b1.x, b1.y, b1.z, b1.w};
            #pragma unroll
            for (int i = 0; i < 8; i++)
                #pragma unroll
                for (int j = 0; j < 8; j++)
                    acc[i][j] = fmaf(ar[i], br[j], acc[i][j]);
        }
        if (more) {
            int nb = buf ^ 1;
            As[nb][ac4 + 0][arow] = ra0.x; As[nb][ac4 + 1][arow] = ra0.y;
            As[nb][ac4 + 2][arow] = ra0.z; As[nb][ac4 + 3][arow] = ra0.w;
            As[nb][ac4 + 0][arow + 64] = ra1.x; As[nb][ac4 + 1][arow + 64] = ra1.y;
            As[nb][ac4 + 2][arow + 64] = ra1.z; As[nb][ac4 + 3][arow + 64] = ra1.w;
            *reinterpret_cast<float4*>(&Bs[nb][brow][bc4]) = rb0;
            *reinterpret_cast<float4*>(&Bs[nb][brow + 8][bc4]) = rb1;
            __syncthreads();
            buf = nb;
        }
    }

    #pragma unroll
    for (int i = 0; i < 8; i++) {
        int m = bm + ty * 8 + i;
        float bv = BIAS ? bias[m] : 0.f;
        #pragma unroll
        for (int j = 0; j < 8; j += 4) {
            float4 v;
            v.x = acc[i][j + 0] + bv; v.y = acc[i][j + 1] + bv;
            v.z = acc[i][j + 2] + bv; v.w = acc[i][j + 3] + bv;
            if (RELU) {
                v.x = fmaxf(v.x, 0.f); v.y = fmaxf(v.y, 0.f);
                v.z = fmaxf(v.z, 0.f); v.w = fmaxf(v.w, 0.f);
            }
            *reinterpret_cast<float4*>(Cb + (size_t)m * N + bn + tx * 8 + j) = v;
        }
    }
}

// ---------------- fold biases: b' = W @ b0 (+extra) -------------------------
__global__ void fold_bias(const float* __restrict__ wqkv,
                          const float* __restrict__ wg1,
                          const float* __restrict__ bg1,
                          const float* __restrict__ b0)
{
    int i = blockIdx.x * 256 + threadIdx.x;
    if (i < 1536) {
        float s = 0.f;
        for (int k = 0; k < 512; k++) s = fmaf(wqkv[(size_t)i * 512 + k], b0[k], s);
        g_bqkv[i] = s;
    } else if (i < 1536 + 256) {
        int j = i - 1536;
        float s = bg1[j];
        for (int k = 0; k < 512; k++) s = fmaf(wg1[(size_t)j * 512 + k], b0[k], s);
        g_bg1[j] = s;
    }
}

// ---------------- depthwise 3x3, SAME, groups = channels -------------------
__global__ void __launch_bounds__(256) dwconv_kernel(
    const float* __restrict__ inp, const float* __restrict__ w,
    float* __restrict__ outp)
{
    const int bc = blockIdx.x;          // b*1536 + ch
    const int ch = bc % 1536;
    const float* ip = inp + (size_t)bc * 4096;
    float*       op = outp + (size_t)bc * 4096;
    __shared__ float sh[66 * 66];
    const int tid = threadIdx.x;
    for (int i = tid; i < 66 * 66; i += 256) {
        int r = i / 66 - 1;
        int c = i % 66 - 1;
        sh[i] = (r >= 0 && r < 64 && c >= 0 && c < 64) ? ip[r * 64 + c] : 0.f;
    }
    const float* wp = w + (size_t)ch * 9;
    float w0 = wp[0], w1 = wp[1], w2 = wp[2];
    float w3 = wp[3], w4 = wp[4], w5 = wp[5];
    float w6 = wp[6], w7 = wp[7], w8 = wp[8];
    __syncthreads();
    #pragma unroll
    for (int j = 0; j < 16; j++) {
        int p = tid + j * 256;
        int y = p >> 6, x = p & 63;
        const float* s0 = &sh[y * 66 + x];
        float acc = s0[0]   * w0 + s0[1]   * w1 + s0[2]   * w2
                  + s0[66]  * w3 + s0[67]  * w4 + s0[68]  * w5
                  + s0[132] * w6 + s0[133] * w7 + s0[134] * w8;
        op[p] = acc;
    }
}

// ---------------- gate: per-pixel sigmoid(dot(g1, wg2)+bg2), partial sums --
__global__ void __launch_bounds__(256) gate_dot(
    const float* __restrict__ g1, const float* __restrict__ wg2,
    const float* __restrict__ bg2)
{
    __shared__ float ws[256];
    __shared__ float red[256];
    const int tid = threadIdx.x;
    ws[tid] = wg2[tid];
    __syncthreads();
    const int P = blockIdx.x * 256 + tid;   // pixel id in [0, 32768)
    const int b = P >> 12;
    const int p = P & 4095;
    const float* base = g1 + (size_t)b * 256 * 4096 + p;
    float acc = bg2[0];
    #pragma unroll 8
    for (int ch = 0; ch < 256; ch++)
        acc = fmaf(base[(size_t)ch * 4096], ws[ch], acc);
    float s = 1.f / (1.f + expf(-acc));
    red[tid] = s;
    __syncthreads();
    for (int st = 128; st > 0; st >>= 1) {
        if (tid < st) red[tid] += red[tid + st];
        __syncthreads();
    }
    if (tid == 0) g_partial[blockIdx.x] = red[0];
}

__global__ void gate_fin()
{
    if (threadIdx.x == 0 && blockIdx.x == 0) {
        float t = 0.f;
        for (int i = 0; i < 128; i++) t += g_partial[i];
        float mean = t * (1.f / 32768.f);
        int k = (int)floorf(64.f * mean);
        k = max(0, min(64, k));
        g_dk = k;
    }
}

// ---------------- row L2 inverse norms for q and k --------------------------
__global__ void __launch_bounds__(256) norm_kernel(const float* __restrict__ qkv)
{
    const int r  = blockIdx.x;           // 0..8191
    const int qk = r >> 12;              // 0 = q, 1 = k
    const int rr = r & 4095;             // b*512 + hc
    const int b  = rr >> 9;
    const int hc = rr & 511;
    const float* p = qkv + ((size_t)b * 1536 + (size_t)qk * 512 + hc) * 4096;
    const int tid = threadIdx.x;
    float s = 0.f;
    for (int i = tid * 4; i < 4096; i += 1024) {
        float4 v = *reinterpret_cast<const float4*>(p + i);
        s += v.x * v.x + v.y * v.y + v.z * v.z + v.w * v.w;
    }
    __shared__ float red[256];
    red[tid] = s;
    __syncthreads();
    for (int st = 128; st > 0; st >>= 1) {
        if (tid < st) red[tid] += red[tid + st];
        __syncthreads();
    }
    if (tid == 0) {
        float inv = 1.f / fmaxf(sqrtf(red[0]), 1e-12f);
        (qk ? g_kinv : g_qinv)[rr] = inv;
    }
}

// ---------------- split-K QK^T partials -------------------------------------
// grid (8 chunks, 64 bh); each block computes 64x64 over 512 spatial positions
__global__ void __launch_bounds__(256) qk_gemm(const float* __restrict__ qkv)
{
    __shared__ float Qt[64 * 68];
    __shared__ float Kt[64 * 68];

    const int bh = blockIdx.y;
    const int b = bh >> 3, h = bh & 7;
    const float* Qg = qkv + ((size_t)b * 1536 + (size_t)h * 64) * 4096;
    const float* Kg = Qg + (size_t)512 * 4096;
    const int n_base = blockIdx.x * 512;

    const int tid = threadIdx.x;
    const int tx = tid & 15, ty = tid >> 4;

    float acc[4][4] = {};
    for (int n0 = n_base; n0 < n_base + 512; n0 += 64) {
        #pragma unroll
        for (int l = 0; l < 4; l++) {
            int f   = tid + l * 256;
            int row = f >> 4;           // c (0..63)
            int nl  = (f & 15) * 4;     // n within tile
            float4 q4 = *reinterpret_cast<const float4*>(
                Qg + (size_t)row * 4096 + n0 + nl);
            float4 k4 = *reinterpret_cast<const float4*>(
                Kg + (size_t)row * 4096 + n0 + nl);
            Qt[(nl + 0) * 68 + row] = q4.x; Qt[(nl + 1) * 68 + row] = q4.y;
            Qt[(nl + 2) * 68 + row] = q4.z; Qt[(nl + 3) * 68 + row] = q4.w;
            Kt[(nl + 0) * 68 + row] = k4.x; Kt[(nl + 1) * 68 + row] = k4.y;
            Kt[(nl + 2) * 68 + row] = k4.z; Kt[(nl + 3) * 68 + row] = k4.w;
        }
        __syncthreads();
        #pragma unroll 8
        for (int nn = 0; nn < 64; nn++) {
            float4 av = *reinterpret_cast<const float4*>(&Qt[nn * 68 + ty * 4]);
            float4 bv = *reinterpret_cast<const float4*>(&Kt[nn * 68 + tx * 4]);
            float ar[4] = {av.x, av.y, av.z, av.w};
            float br[4] = {bv.x, bv.y, bv.z, bv.w};
            #pragma unroll
            for (int i = 0; i < 4; i++)
                #pragma unroll
                for (int j = 0; j < 4; j++)
                    acc[i][j] = fmaf(ar[i], br[j], acc[i][j]);
        }
        __syncthreads();
    }
    float* Sp = &g_Spart[((size_t)blockIdx.x * 64 + bh) * 4096];
    #pragma unroll
    for (int i = 0; i < 4; i++) {
        float4 v;
        v.x = acc[i][0]; v.y = acc[i][1]; v.z = acc[i][2]; v.w = acc[i][3];
        *reinterpret_cast<float4*>(&Sp[(ty * 4 + i) * 64 + tx * 4]) = v;
    }
}

// ---------------- reduce partials + scale + top-k + softmax ----------------
// grid 64 (bh), block 256
__global__ void __launch_bounds__(256) topk_softmax(const float* __restrict__ temp)
{
    __shared__ float S[64 * 65];
    const int bh = blockIdx.x;
    const int b = bh >> 3, h = bh & 7;
    const int tid = threadIdx.x;
    const int base = b * 512 + h * 64;
    const float tmp = temp[h];

    // reduce 8 chunks, apply scaling
    for (int e = tid; e < 4096; e += 256) {
        float s = 0.f;
        #pragma unroll
        for (int c = 0; c < 8; c++)
            s += g_Spart[((size_t)c * 64 + bh) * 4096 + e];
        int row = e >> 6, col = e & 63;
        S[row * 65 + col] = s * g_qinv[base + row] * tmp * g_kinv[base + col];
    }
    __syncthreads();

    const int kd = g_dk;
    if (tid < 64) {
        float* row = &S[tid * 65];
        float m = -INFINITY;
        unsigned long long keep = 0ull;
        for (int i = 0; i < 64; i++) {
            float ai = row[i];
            int cnt = 0;
            for (int j = 0; j < 64; j++) {
                float aj = row[j];
                cnt += (aj > ai) ? 1 : ((aj == ai && j < i) ? 1 : 0);
            }
            if (cnt < kd) { keep |= (1ull << i); m = fmaxf(m, ai); }
        }
        float s = 0.f;
        for (int i = 0; i < 64; i++) {
            float e = ((keep >> i) & 1ull) ? expf(row[i] - m) : 0.f;
            row[i] = e;
            s += e;
        }
        float inv = (s > 0.f) ? 1.f / s : 0.f;
        for (int i = 0; i < 64; i++) row[i] *= inv;
    }
    __syncthreads();
    for (int e = tid; e < 4096; e += 256) {
        int row = e >> 6, col = e & 63;
        g_P[(size_t)bh * 4096 + e] = S[row * 65 + col];
    }
}

// ---------------- out = sc * P @ V ------------------------------------------
// grid (8 chunks, 64 bh)
__global__ void __launch_bounds__(256) av_gemm(
    const float* __restrict__ qkv,
    const float* __restrict__ a1p, const float* __restrict__ a2p,
    const float* __restrict__ a3p, const float* __restrict__ a4p,
    float* __restrict__ outp)
{
    __shared__ float P[64 * 65];
    __shared__ float Vt[64 * 68];

    const int bh = blockIdx.y;
    const int b = bh >> 3, h = bh & 7;
    const float* Vg = qkv + ((size_t)b * 1536 + 1024 + (size_t)h * 64) * 4096;
    float* Og = outp + ((size_t)b * 512 + (size_t)h * 64) * 4096;
    const int n_base = blockIdx.x * 512;
    const float sc = a1p[0] + a2p[0] + a3p[0] + a4p[0];

    const int tid = threadIdx.x;
    const int tx = tid & 15, ty = tid >> 4;

    for (int e = tid; e < 4096; e += 256) {
        int row = e >> 6, col = e & 63;
        P[row * 65 + col] = g_P[(size_t)bh * 4096 + e];
    }
    __syncthreads();

    for (int n0 = n_base; n0 < n_base + 512; n0 += 64) {
        #pragma unroll
        for (int l = 0; l < 4; l++) {
            int f   = tid + l * 256;
            int row = f >> 4;           // d
            int nl  = (f & 15) * 4;
            *reinterpret_cast<float4*>(&Vt[row * 68 + nl]) =
                *reinterpret_cast<const float4*>(
                    Vg + (size_t)row * 4096 + n0 + nl);
        }
        __syncthreads();
        float o[4][4] = {};
        #pragma unroll 4
        for (int d = 0; d < 64; d++) {
            float s0 = P[(ty * 4 + 0) * 65 + d];
            float s1 = P[(ty * 4 + 1) * 65 + d];
            float s2 = P[(ty * 4 + 2) * 65 + d];
            float s3 = P[(ty * 4 + 3) * 65 + d];
            float4 v4 = *reinterpret_cast<const float4*>(&Vt[d * 68 + tx * 4]);
            o[0][0] = fmaf(s0, v4.x, o[0][0]); o[0][1] = fmaf(s0, v4.y, o[0][1]);
            o[0][2] = fmaf(s0, v4.z, o[0][2]); o[0][3] = fmaf(s0, v4.w, o[0][3]);
            o[1][0] = fmaf(s1, v4.x, o[1][0]); o[1][1] = fmaf(s1, v4.y, o[1][1]);
            o[1][2] = fmaf(s1, v4.z, o[1][2]); o[1][3] = fmaf(s1, v4.w, o[1][3]);
            o[2][0] = fmaf(s2, v4.x, o[2][0]); o[2][1] = fmaf(s2, v4.y, o[2][1]);
            o[2][2] = fmaf(s2, v4.z, o[2][2]); o[2][3] = fmaf(s2, v4.w, o[2][3]);
            o[3][0] = fmaf(s3, v4.x, o[3][0]); o[3][1] = fmaf(s3, v4.y, o[3][1]);
            o[3][2] = fmaf(s3, v4.z, o[3][2]); o[3][3] = fmaf(s3, v4.w, o[3][3]);
        }
        #pragma unroll
        for (int i = 0; i < 4; i++) {
            float4 w;
            w.x = o[i][0] * sc; w.y = o[i][1] * sc;
            w.z = o[i][2] * sc; w.w = o[i][3] * sc;
            *reinterpret_cast<float4*>(
                Og + (size_t)(ty * 4 + i) * 4096 + n0 + tx * 4) = w;
        }
        __syncthreads();
    }
}

// ---------------------------------------------------------------------------
extern "C" void kernel_launch(void* const* d_in, const int* in_sizes, int n_in,
                              void* d_out, int out_size)
{
    const float* x    = (const float*)d_in[0];
    const float* w0   = (const float*)d_in[1];
    const float* b0   = (const float*)d_in[2];
    const float* wqkv = (const float*)d_in[3];
    const float* wdw  = (const float*)d_in[4];
    const float* temp = (const float*)d_in[5];
    const float* wg1  = (const float*)d_in[6];
    const float* bg1  = (const float*)d_in[7];
    const float* wg2  = (const float*)d_in[8];
    const float* bg2  = (const float*)d_in[9];
    const float* a1   = (const float*)d_in[10];
    const float* a2   = (const float*)d_in[11];
    const float* a3   = (const float*)d_in[12];
    const float* a4   = (const float*)d_in[13];
    float* out = (float*)d_out;

    float *Wqkv, *Wg1, *bqkv, *bg1f, *qkvp, *qkvb, *g1;
    cudaGetSymbolAddress((void**)&Wqkv, g_Wqkv);
    cudaGetSymbolAddress((void**)&Wg1,  g_Wg1);
    cudaGetSymbolAddress((void**)&bqkv, g_bqkv);
    cudaGetSymbolAddress((void**)&bg1f, g_bg1);
    cudaGetSymbolAddress((void**)&qkvp, g_qkvp);
    cudaGetSymbolAddress((void**)&qkvb, g_qkv);
    cudaGetSymbolAddress((void**)&g1,   g_g1);

    dim3 blk(256);

    // fold weights: Wqkv' = wqkv @ w0 [1536,512], Wg1' = wg1 @ w0 [256,512]
    sgemm_db<false, false><<<dim3(4, 12, 1), blk>>>(
        wqkv, w0, nullptr, Wqkv, 1536, 512, 512, 0, 0);
    sgemm_db<false, false><<<dim3(4, 2, 1), blk>>>(
        wg1, w0, nullptr, Wg1, 256, 512, 512, 0, 0);
    fold_bias<<<8, blk>>>(wqkv, wg1, bg1, b0);

    // qkv_pre = Wqkv' @ x + bqkv'       [1536,512] x [512,4096] per batch
    sgemm_db<false, true><<<dim3(32, 12, 8), blk>>>(
        Wqkv, x, bqkv, qkvp, 1536, 4096, 512,
        (size_t)512 * 4096, (size_t)1536 * 4096);

    // g1 = relu(Wg1' @ x + bg1')        [256,512] x [512,4096] per batch
    sgemm_db<true, true><<<dim3(32, 2, 8), blk>>>(
        Wg1, x, bg1f, g1, 256, 4096, 512,
        (size_t)512 * 4096, (size_t)256 * 4096);

    // depthwise 3x3 SAME
    dwconv_kernel<<<8 * 1536, blk>>>(qkvp, wdw, qkvb);

    // dynamic_k = floor(64 * mean(sigmoid(g1 . wg2 + bg2)))
    gate_dot<<<128, blk>>>(g1, wg2, bg2);
    gate_fin<<<1, 32>>>();

    // inverse L2 norms of q and k rows
    norm_kernel<<<8192, blk>>>(qkvb);

    // split-K QK^T partials, reduce+topk+softmax, then P@V
    qk_gemm<<<dim3(8, 64), blk>>>(qkvb);
    topk_softmax<<<64, blk>>>(temp);
    av_gemm<<<dim3(8, 64), blk>>>(qkvb, a1, a2, a3, a4, out);
}

// round 4
// speedup vs baseline: 1.7007x; 1.3246x over previous
#include <cuda_runtime.h>
#include <cuda_bf16.h>
#include <mma.h>
#include <math.h>
#include <cstdint>

using namespace nvcuda;

// ---------------- scratch (static device globals; no allocations) ----------
__device__ float g_Wqkv[786432];     // [1536,512]  wqkv@w0 (fp32 fold)
__device__ float g_Wg1[131072];      // [256,512]   wg1@w0  (fp32 fold)
__device__ float g_bqkv[1536];       // wqkv@b0
__device__ float g_bg1[256];         // bg1 + wg1@b0
__device__ __nv_bfloat16 g_Wqkv_hi[786432];
__device__ __nv_bfloat16 g_Wqkv_lo[786432];
__device__ __nv_bfloat16 g_Wg1_hi[131072];
__device__ __nv_bfloat16 g_Wg1_lo[131072];
__device__ __nv_bfloat16 g_Xhi[16777216];  // [8,512,4096]
__device__ __nv_bfloat16 g_Xlo[16777216];
__device__ float g_qkvp[50331648];   // [8,1536,4096] pre-depthwise qkv (no bias)
__device__ float g_qkv[50331648];    // [8,1536,4096] post-depthwise qkv
__device__ float g_g1[8388608];      // [8,256,4096]  raw gate conv1 (no bias/relu)
__device__ float g_partial[128];
__device__ float g_qinv[4096];
__device__ float g_kinv[4096];
__device__ float g_Spart[2097152];   // [8 chunk][64 bh][64][64]
__device__ float g_P[262144];        // [64 bh][64][64]
__device__ int   g_dk;

// ============ wmma bf16x3 GEMM: C = W @ X, K=1536 = 3x512 segments ==========
// seg0: Whi*Xhi, seg1: Wlo*Xhi, seg2: Whi*Xlo. Raw fp32 out (bias fused later).
// CTA: 128(M) x 128(N); 8 warps, warp tile 64x32; BK=32.
static constexpr int LDA = 40;    // As row stride (bf16)
static constexpr int LDB = 136;   // Bs row stride (bf16)

__global__ void __launch_bounds__(256) mma_gemm(
    const __nv_bfloat16* __restrict__ Whi, const __nv_bfloat16* __restrict__ Wlo,
    const __nv_bfloat16* __restrict__ Xhi, const __nv_bfloat16* __restrict__ Xlo,
    float* __restrict__ C, int Mtotal)
{
    __shared__ __nv_bfloat16 As[2][128 * LDA];
    __shared__ __nv_bfloat16 Bs[2][32 * LDB];

    const int tid = threadIdx.x;
    const int wid = tid >> 5;
    const int wm = wid >> 2;          // 0..1  -> rows wm*64
    const int wn = wid & 3;           // 0..3  -> cols wn*32

    const int n0 = blockIdx.x << 7;
    const int bm = blockIdx.y << 7;
    const int batch = blockIdx.z;

    const __nv_bfloat16* Xb_hi = Xhi + (size_t)batch * 512 * 4096;
    const __nv_bfloat16* Xb_lo = Xlo + (size_t)batch * 512 * 4096;

    // per-thread load coords
    const int arow = tid >> 2, aq = (tid & 3) * 8;         // + 64 rows second
    const int brow = tid >> 4, bq = (tid & 15) * 8;        // + 16 rows second

    wmma::fragment<wmma::accumulator, 16, 16, 16, float> acc[4][2];
    #pragma unroll
    for (int i = 0; i < 4; i++)
        #pragma unroll
        for (int j = 0; j < 2; j++) wmma::fill_fragment(acc[i][j], 0.f);

    auto loadChunk = [&](int c, uint4& a0, uint4& a1, uint4& b0, uint4& b1) {
        const int seg = c >> 4;
        const int kk = (c & 15) << 5;
        const __nv_bfloat16* Aseg = (seg == 1 ? Wlo : Whi) + (size_t)bm * 512;
        const __nv_bfloat16* Bseg = (seg == 2 ? Xb_lo : Xb_hi);
        a0 = *reinterpret_cast<const uint4*>(Aseg + (size_t)arow * 512 + kk + aq);
        a1 = *reinterpret_cast<const uint4*>(Aseg + (size_t)(arow + 64) * 512 + kk + aq);
        b0 = *reinterpret_cast<const uint4*>(Bseg + (size_t)(kk + brow) * 4096 + n0 + bq);
        b1 = *reinterpret_cast<const uint4*>(Bseg + (size_t)(kk + brow + 16) * 4096 + n0 + bq);
    };
    auto storeChunk = [&](int buf, const uint4& a0, const uint4& a1,
                          const uint4& b0, const uint4& b1) {
        *reinterpret_cast<uint4*>(&As[buf][arow * LDA + aq]) = a0;
        *reinterpret_cast<uint4*>(&As[buf][(arow + 64) * LDA + aq]) = a1;
        *reinterpret_cast<uint4*>(&Bs[buf][brow * LDB + bq]) = b0;
        *reinterpret_cast<uint4*>(&Bs[buf][(brow + 16) * LDB + bq]) = b1;
    };

    {
        uint4 a0, a1, b0, b1;
        loadChunk(0, a0, a1, b0, b1);
        storeChunk(0, a0, a1, b0, b1);
    }
    __syncthreads();

    int buf = 0;
    for (int c = 0; c < 48; c++) {
        uint4 a0, a1, b0, b1;
        const bool more = (c + 1) < 48;
        if (more) loadChunk(c + 1, a0, a1, b0, b1);

        #pragma unroll
        for (int ks = 0; ks < 2; ks++) {
            wmma::fragment<wmma::matrix_a, 16, 16, 16, __nv_bfloat16, wmma::row_major> af[4];
            wmma::fragment<wmma::matrix_b, 16, 16, 16, __nv_bfloat16, wmma::row_major> bf[2];
            #pragma unroll
            for (int mi = 0; mi < 4; mi++)
                wmma::load_matrix_sync(af[mi],
                    &As[buf][(wm * 64 + mi * 16) * LDA + ks * 16], LDA);
            #pragma unroll
            for (int ni = 0; ni < 2; ni++)
                wmma::load_matrix_sync(bf[ni],
                    &Bs[buf][(ks * 16) * LDB + wn * 32 + ni * 16], LDB);
            #pragma unroll
            for (int mi = 0; mi < 4; mi++)
                #pragma unroll
                for (int ni = 0; ni < 2; ni++)
                    wmma::mma_sync(acc[mi][ni], af[mi], bf[ni], acc[mi][ni]);
        }
        if (more) {
            storeChunk(buf ^ 1, a0, a1, b0, b1);
            __syncthreads();
            buf ^= 1;
        }
    }

    float* Cb = C + (size_t)batch * Mtotal * 4096;
    #pragma unroll
    for (int mi = 0; mi < 4; mi++)
        #pragma unroll
        for (int ni = 0; ni < 2; ni++)
            wmma::store_matrix_sync(
                Cb + (size_t)(bm + wm * 64 + mi * 16) * 4096 + n0 + wn * 32 + ni * 16,
                acc[mi][ni], 4096, wmma::mem_row_major);
}

// ---------------- split fp32 -> bf16 hi/lo ----------------------------------
__global__ void split_kernel(const float* __restrict__ in,
                             __nv_bfloat16* __restrict__ hi,
                             __nv_bfloat16* __restrict__ lo, int n)
{
    int i = blockIdx.x * 256 + threadIdx.x;
    if (i < n) {
        float v = in[i];
        __nv_bfloat16 h = __float2bfloat16(v);
        hi[i] = h;
        lo[i] = __float2bfloat16(v - __bfloat162float(h));
    }
}

// ---------------- fp32 fold GEMM (small; weight folding only) ---------------
template<bool RELU, bool BIAS>
__global__ void __launch_bounds__(256) sgemm_db(
    const float* __restrict__ A, const float* __restrict__ Bm,
    const float* __restrict__ bias, float* __restrict__ C,
    int M, int N, int K, size_t sB, size_t sC)
{
    constexpr int BM = 128, BN = 128, BK = 16;
    __shared__ float As[2][BK][BM];
    __shared__ float Bs[2][BK][BN];

    const float* Bb = Bm + (size_t)blockIdx.z * sB;
    float*       Cb = C  + (size_t)blockIdx.z * sC;
    const int bm = blockIdx.y * BM;
    const int bn = blockIdx.x * BN;
    const int tid = threadIdx.x;
    const int tx = tid & 15;
    const int ty = tid >> 4;

    const int arow = tid >> 2;
    const int ac4  = (tid & 3) * 4;
    const int brow = tid >> 5;
    const int bc4  = (tid & 31) * 4;

    float4 ra0, ra1, rb0, rb1;
    ra0 = *reinterpret_cast<const float4*>(A + (size_t)(bm + arow) * K + ac4);
    ra1 = *reinterpret_cast<const float4*>(A + (size_t)(bm + arow + 64) * K + ac4);
    rb0 = *reinterpret_cast<const float4*>(Bb + (size_t)(brow) * N + bn + bc4);
    rb1 = *reinterpret_cast<const float4*>(Bb + (size_t)(brow + 8) * N + bn + bc4);
    As[0][ac4 + 0][arow] = ra0.x; As[0][ac4 + 1][arow] = ra0.y;
    As[0][ac4 + 2][arow] = ra0.z; As[0][ac4 + 3][arow] = ra0.w;
    As[0][ac4 + 0][arow + 64] = ra1.x; As[0][ac4 + 1][arow + 64] = ra1.y;
    As[0][ac4 + 2][arow + 64] = ra1.z; As[0][ac4 + 3][arow + 64] = ra1.w;
    *reinterpret_cast<float4*>(&Bs[0][brow][bc4]) = rb0;
    *reinterpret_cast<float4*>(&Bs[0][brow + 8][bc4]) = rb1;
    __syncthreads();

    float acc[8][8] = {};
    int buf = 0;
    for (int k0 = 0; k0 < K; k0 += BK) {
        const bool more = (k0 + BK) < K;
        if (more) {
            int kn = k0 + BK;
            ra0 = *reinterpret_cast<const float4*>(A + (size_t)(bm + arow) * K + kn + ac4);
            ra1 = *reinterpret_cast<const float4*>(A + (size_t)(bm + arow + 64) * K + kn + ac4);
            rb0 = *reinterpret_cast<const float4*>(Bb + (size_t)(kn + brow) * N + bn + bc4);
            rb1 = *reinterpret_cast<const float4*>(Bb + (size_t)(kn + brow + 8) * N + bn + bc4);
        }
        #pragma unroll
        for (int kk = 0; kk < BK; kk++) {
            float4 a0 = *reinterpret_cast<const float4*>(&As[buf][kk][ty * 8]);
            float4 a1 = *reinterpret_cast<const float4*>(&As[buf][kk][ty * 8 + 4]);
            float4 b0 = *reinterpret_cast<const float4*>(&Bs[buf][kk][tx * 8]);
            float4 b1 = *reinterpret_cast<const float4*>(&Bs[buf][kk][tx * 8 + 4]);
            float ar[8] = {a0.x, a0.y, a0.z, a0.w, a1.x, a1.y, a1.z, a1.w};
            float br[8] = {b0.x, b0.y, b0.z, b0.w, b1.x, b1.y, b1.z, b1.w};
            #pragma unroll
            for (int i = 0; i < 8; i++)
                #pragma unroll
                for (int j = 0; j < 8; j++)
                    acc[i][j] = fmaf(ar[i], br[j], acc[i][j]);
        }
        if (more) {
            int nb = buf ^ 1;
            As[nb][ac4 + 0][arow] = ra0.x; As[nb][ac4 + 1][arow] = ra0.y;
            As[nb][ac4 + 2][arow] = ra0.z; As[nb][ac4 + 3][arow] = ra0.w;
            As[nb][ac4 + 0][arow + 64] = ra1.x; As[nb][ac4 + 1][arow + 64] = ra1.y;
            As[nb][ac4 + 2][arow + 64] = ra1.z; As[nb][ac4 + 3][arow + 64] = ra1.w;
            *reinterpret_cast<float4*>(&Bs[nb][brow][bc4]) = rb0;
            *reinterpret_cast<float4*>(&Bs[nb][brow + 8][bc4]) = rb1;
            __syncthreads();
            buf = nb;
        }
    }
    #pragma unroll
    for (int i = 0; i < 8; i++) {
        int m = bm + ty * 8 + i;
        float bv = BIAS ? bias[m] : 0.f;
        #pragma unroll
        for (int j = 0; j < 8; j += 4) {
            float4 v;
            v.x = acc[i][j + 0] + bv; v.y = acc[i][j + 1] + bv;
            v.z = acc[i][j + 2] + bv; v.w = acc[i][j + 3] + bv;
            if (RELU) {
                v.x = fmaxf(v.x, 0.f); v.y = fmaxf(v.y, 0.f);
                v.z = fmaxf(v.z, 0.f); v.w = fmaxf(v.w, 0.f);
            }
            *reinterpret_cast<float4*>(Cb + (size_t)m * N + bn + tx * 8 + j) = v;
        }
    }
}

// ---------------- fold biases -----------------------------------------------
__global__ void fold_bias(const float* __restrict__ wqkv,
                          const float* __restrict__ wg1,
                          const float* __restrict__ bg1,
                          const float* __restrict__ b0)
{
    int i = blockIdx.x * 256 + threadIdx.x;
    if (i < 1536) {
        float s = 0.f;
        for (int k = 0; k < 512; k++) s = fmaf(wqkv[(size_t)i * 512 + k], b0[k], s);
        g_bqkv[i] = s;
    } else if (i < 1536 + 256) {
        int j = i - 1536;
        float s = bg1[j];
        for (int k = 0; k < 512; k++) s = fmaf(wg1[(size_t)j * 512 + k], b0[k], s);
        g_bg1[j] = s;
    }
}

// ---------------- depthwise 3x3 SAME, bias fused at load --------------------
__global__ void __launch_bounds__(256) dwconv_kernel(
    const float* __restrict__ inp, const float* __restrict__ w,
    const float* __restrict__ bias, float* __restrict__ outp)
{
    const int bc = blockIdx.x;
    const int ch = bc % 1536;
    const float* ip = inp + (size_t)bc * 4096;
    float*       op = outp + (size_t)bc * 4096;
    __shared__ float sh[66 * 66];
    const int tid = threadIdx.x;
    const float bv = bias[ch];
    for (int i = tid; i < 66 * 66; i += 256) {
        int r = i / 66 - 1;
        int c = i % 66 - 1;
        sh[i] = (r >= 0 && r < 64 && c >= 0 && c < 64) ? ip[r * 64 + c] + bv : 0.f;
    }
    const float* wp = w + (size_t)ch * 9;
    float w0 = wp[0], w1 = wp[1], w2 = wp[2];
    float w3 = wp[3], w4 = wp[4], w5 = wp[5];
    float w6 = wp[6], w7 = wp[7], w8 = wp[8];
    __syncthreads();
    #pragma unroll
    for (int j = 0; j < 16; j++) {
        int p = tid + j * 256;
        int y = p >> 6, x = p & 63;
        const float* s0 = &sh[y * 66 + x];
        op[p] = s0[0]   * w0 + s0[1]   * w1 + s0[2]   * w2
              + s0[66]  * w3 + s0[67]  * w4 + s0[68]  * w5
              + s0[132] * w6 + s0[133] * w7 + s0[134] * w8;
    }
}

// ---------------- gate: bias+relu fused, sigmoid dot, partial sums ----------
__global__ void __launch_bounds__(256) gate_dot(
    const float* __restrict__ g1, const float* __restrict__ wg2,
    const float* __restrict__ bg1f, const float* __restrict__ bg2)
{
    __shared__ float ws[256];
    __shared__ float bs[256];
    __shared__ float red[256];
    const int tid = threadIdx.x;
    ws[tid] = wg2[tid];
    bs[tid] = bg1f[tid];
    __syncthreads();
    const int P = blockIdx.x * 256 + tid;
    const int b = P >> 12;
    const int p = P & 4095;
    const float* base = g1 + (size_t)b * 256 * 4096 + p;
    float acc = bg2[0];
    #pragma unroll 8
    for (int ch = 0; ch < 256; ch++)
        acc = fmaf(fmaxf(base[(size_t)ch * 4096] + bs[ch], 0.f), ws[ch], acc);
    float s = 1.f / (1.f + expf(-acc));
    red[tid] = s;
    __syncthreads();
    for (int st = 128; st > 0; st >>= 1) {
        if (tid < st) red[tid] += red[tid + st];
        __syncthreads();
    }
    if (tid == 0) g_partial[blockIdx.x] = red[0];
}

__global__ void gate_fin()
{
    if (threadIdx.x == 0 && blockIdx.x == 0) {
        float t = 0.f;
        for (int i = 0; i < 128; i++) t += g_partial[i];
        float mean = t * (1.f / 32768.f);
        int k = (int)floorf(64.f * mean);
        g_dk = max(0, min(64, k));
    }
}

// ---------------- row L2 inverse norms --------------------------------------
__global__ void __launch_bounds__(256) norm_kernel(const float* __restrict__ qkv)
{
    const int r  = blockIdx.x;
    const int qk = r >> 12;
    const int rr = r & 4095;
    const int b  = rr >> 9;
    const int hc = rr & 511;
    const float* p = qkv + ((size_t)b * 1536 + (size_t)qk * 512 + hc) * 4096;
    const int tid = threadIdx.x;
    float s = 0.f;
    for (int i = tid * 4; i < 4096; i += 1024) {
        float4 v = *reinterpret_cast<const float4*>(p + i);
        s += v.x * v.x + v.y * v.y + v.z * v.z + v.w * v.w;
    }
    __shared__ float red[256];
    red[tid] = s;
    __syncthreads();
    for (int st = 128; st > 0; st >>= 1) {
        if (tid < st) red[tid] += red[tid + st];
        __syncthreads();
    }
    if (tid == 0) {
        float inv = 1.f / fmaxf(sqrtf(red[0]), 1e-12f);
        (qk ? g_kinv : g_qinv)[rr] = inv;
    }
}

// ---------------- split-K QK^T partials --------------------------------------
__global__ void __launch_bounds__(256) qk_gemm(const float* __restrict__ qkv)
{
    __shared__ float Qt[64 * 68];
    __shared__ float Kt[64 * 68];

    const int bh = blockIdx.y;
    const int b = bh >> 3, h = bh & 7;
    const float* Qg = qkv + ((size_t)b * 1536 + (size_t)h * 64) * 4096;
    const float* Kg = Qg + (size_t)512 * 4096;
    const int n_base = blockIdx.x * 512;

    const int tid = threadIdx.x;
    const int tx = tid & 15, ty = tid >> 4;

    float acc[4][4] = {};
    for (int n0 = n_base; n0 < n_base + 512; n0 += 64) {
        #pragma unroll
        for (int l = 0; l < 4; l++) {
            int f   = tid + l * 256;
            int row = f >> 4;
            int nl  = (f & 15) * 4;
            float4 q4 = *reinterpret_cast<const float4*>(Qg + (size_t)row * 4096 + n0 + nl);
            float4 k4 = *reinterpret_cast<const float4*>(Kg + (size_t)row * 4096 + n0 + nl);
            Qt[(nl + 0) * 68 + row] = q4.x; Qt[(nl + 1) * 68 + row] = q4.y;
            Qt[(nl + 2) * 68 + row] = q4.z; Qt[(nl + 3) * 68 + row] = q4.w;
            Kt[(nl + 0) * 68 + row] = k4.x; Kt[(nl + 1) * 68 + row] = k4.y;
            Kt[(nl + 2) * 68 + row] = k4.z; Kt[(nl + 3) * 68 + row] = k4.w;
        }
        __syncthreads();
        #pragma unroll 8
        for (int nn = 0; nn < 64; nn++) {
            float4 av = *reinterpret_cast<const float4*>(&Qt[nn * 68 + ty * 4]);
            float4 bv = *reinterpret_cast<const float4*>(&Kt[nn * 68 + tx * 4]);
            float ar[4] = {av.x, av.y, av.z, av.w};
            float br[4] = {bv.x, bv.y, bv.z, bv.w};
            #pragma unroll
            for (int i = 0; i < 4; i++)
                #pragma unroll
                for (int j = 0; j < 4; j++)
                    acc[i][j] = fmaf(ar[i], br[j], acc[i][j]);
        }
        __syncthreads();
    }
    float* Sp = &g_Spart[((size_t)blockIdx.x * 64 + bh) * 4096];
    #pragma unroll
    for (int i = 0; i < 4; i++) {
        float4 v;
        v.x = acc[i][0]; v.y = acc[i][1]; v.z = acc[i][2]; v.w = acc[i][3];
        *reinterpret_cast<float4*>(&Sp[(ty * 4 + i) * 64 + tx * 4]) = v;
    }
}

// ---------------- reduce + scale + top-k + softmax ---------------------------
__global__ void __launch_bounds__(256) topk_softmax(const float* __restrict__ temp)
{
    __shared__ float S[64 * 65];
    const int bh = blockIdx.x;
    const int b = bh >> 3, h = bh & 7;
    const int tid = threadIdx.x;
    const int base = b * 512 + h * 64;
    const float tmp = temp[h];

    for (int e = tid; e < 4096; e += 256) {
        float s = 0.f;
        #pragma unroll
        for (int c = 0; c < 8; c++)
            s += g_Spart[((size_t)c * 64 + bh) * 4096 + e];
        int row = e >> 6, col = e & 63;
        S[row * 65 + col] = s * g_qinv[base + row] * tmp * g_kinv[base + col];
    }
    __syncthreads();

    const int kd = g_dk;
    if (tid < 64) {
        float* row = &S[tid * 65];
        float m = -INFINITY;
        unsigned long long keep = 0ull;
        for (int i = 0; i < 64; i++) {
            float ai = row[i];
            int cnt = 0;
            for (int j = 0; j < 64; j++) {
                float aj = row[j];
                cnt += (aj > ai) ? 1 : ((aj == ai && j < i) ? 1 : 0);
            }
            if (cnt < kd) { keep |= (1ull << i); m = fmaxf(m, ai); }
        }
        float s = 0.f;
        for (int i = 0; i < 64; i++) {
            float e = ((keep >> i) & 1ull) ? expf(row[i] - m) : 0.f;
            row[i] = e;
            s += e;
        }
        float inv = (s > 0.f) ? 1.f / s : 0.f;
        for (int i = 0; i < 64; i++) row[i] *= inv;
    }
    __syncthreads();
    for (int e = tid; e < 4096; e += 256) {
        int row = e >> 6, col = e & 63;
        g_P[(size_t)bh * 4096 + e] = S[row * 65 + col];
    }
}

// ---------------- out = sc * P @ V -------------------------------------------
__global__ void __launch_bounds__(256) av_gemm(
    const float* __restrict__ qkv,
    const float* __restrict__ a1p, const float* __restrict__ a2p,
    const float* __restrict__ a3p, const float* __restrict__ a4p,
    float* __restrict__ outp)
{
    __shared__ float P[64 * 65];
    __shared__ float Vt[64 * 68];

    const int bh = blockIdx.y;
    const int b = bh >> 3, h = bh & 7;
    const float* Vg = qkv + ((size_t)b * 1536 + 1024 + (size_t)h * 64) * 4096;
    float* Og = outp + ((size_t)b * 512 + (size_t)h * 64) * 4096;
    const int n_base = blockIdx.x * 512;
    const float sc = a1p[0] + a2p[0] + a3p[0] + a4p[0];

    const int tid = threadIdx.x;
    const int tx = tid & 15, ty = tid >> 4;

    for (int e = tid; e < 4096; e += 256) {
        int row = e >> 6, col = e & 63;
        P[row * 65 + col] = g_P[(size_t)bh * 4096 + e];
    }
    __syncthreads();

    for (int n0 = n_base; n0 < n_base + 512; n0 += 64) {
        #pragma unroll
        for (int l = 0; l < 4; l++) {
            int f   = tid + l * 256;
            int row = f >> 4;
            int nl  = (f & 15) * 4;
            *reinterpret_cast<float4*>(&Vt[row * 68 + nl]) =
                *reinterpret_cast<const float4*>(Vg + (size_t)row * 4096 + n0 + nl);
        }
        __syncthreads();
        float o[4][4] = {};
        #pragma unroll 4
        for (int d = 0; d < 64; d++) {
            float s0 = P[(ty * 4 + 0) * 65 + d];
            float s1 = P[(ty * 4 + 1) * 65 + d];
            float s2 = P[(ty * 4 + 2) * 65 + d];
            float s3 = P[(ty * 4 + 3) * 65 + d];
            float4 v4 = *reinterpret_cast<const float4*>(&Vt[d * 68 + tx * 4]);
            o[0][0] = fmaf(s0, v4.x, o[0][0]); o[0][1] = fmaf(s0, v4.y, o[0][1]);
            o[0][2] = fmaf(s0, v4.z, o[0][2]); o[0][3] = fmaf(s0, v4.w, o[0][3]);
            o[1][0] = fmaf(s1, v4.x, o[1][0]); o[1][1] = fmaf(s1, v4.y, o[1][1]);
            o[1][2] = fmaf(s1, v4.z, o[1][2]); o[1][3] = fmaf(s1, v4.w, o[1][3]);
            o[2][0] = fmaf(s2, v4.x, o[2][0]); o[2][1] = fmaf(s2, v4.y, o[2][1]);
            o[2][2] = fmaf(s2, v4.z, o[2][2]); o[2][3] = fmaf(s2, v4.w, o[2][3]);
            o[3][0] = fmaf(s3, v4.x, o[3][0]); o[3][1] = fmaf(s3, v4.y, o[3][1]);
            o[3][2] = fmaf(s3, v4.z, o[3][2]); o[3][3] = fmaf(s3, v4.w, o[3][3]);
        }
        #pragma unroll
        for (int i = 0; i < 4; i++) {
            float4 w;
            w.x = o[i][0] * sc; w.y = o[i][1] * sc;
            w.z = o[i][2] * sc; w.w = o[i][3] * sc;
            *reinterpret_cast<float4*>(Og + (size_t)(ty * 4 + i) * 4096 + n0 + tx * 4) = w;
        }
        __syncthreads();
    }
}

// ---------------------------------------------------------------------------
extern "C" void kernel_launch(void* const* d_in, const int* in_sizes, int n_in,
                              void* d_out, int out_size)
{
    const float* x    = (const float*)d_in[0];
    const float* w0   = (const float*)d_in[1];
    const float* b0   = (const float*)d_in[2];
    const float* wqkv = (const float*)d_in[3];
    const float* wdw  = (const float*)d_in[4];
    const float* temp = (const float*)d_in[5];
    const float* wg1  = (const float*)d_in[6];
    const float* bg1  = (const float*)d_in[7];
    const float* wg2  = (const float*)d_in[8];
    const float* bg2  = (const float*)d_in[9];
    const float* a1   = (const float*)d_in[10];
    const float* a2   = (const float*)d_in[11];
    const float* a3   = (const float*)d_in[12];
    const float* a4   = (const float*)d_in[13];
    float* out = (float*)d_out;

    float *Wqkv, *Wg1, *bqkv, *bg1f, *qkvp, *qkvb, *g1;
    __nv_bfloat16 *Wqh, *Wql, *Wgh, *Wgl, *Xh, *Xl;
    cudaGetSymbolAddress((void**)&Wqkv, g_Wqkv);
    cudaGetSymbolAddress((void**)&Wg1,  g_Wg1);
    cudaGetSymbolAddress((void**)&bqkv, g_bqkv);
    cudaGetSymbolAddress((void**)&bg1f, g_bg1);
    cudaGetSymbolAddress((void**)&qkvp, g_qkvp);
    cudaGetSymbolAddress((void**)&qkvb, g_qkv);
    cudaGetSymbolAddress((void**)&g1,   g_g1);
    cudaGetSymbolAddress((void**)&Wqh,  g_Wqkv_hi);
    cudaGetSymbolAddress((void**)&Wql,  g_Wqkv_lo);
    cudaGetSymbolAddress((void**)&Wgh,  g_Wg1_hi);
    cudaGetSymbolAddress((void**)&Wgl,  g_Wg1_lo);
    cudaGetSymbolAddress((void**)&Xh,   g_Xhi);
    cudaGetSymbolAddress((void**)&Xl,   g_Xlo);

    dim3 blk(256);

    // fold weights (fp32, small)
    sgemm_db<false, false><<<dim3(4, 12, 1), blk>>>(wqkv, w0, nullptr, Wqkv, 1536, 512, 512, 0, 0);
    sgemm_db<false, false><<<dim3(4, 2, 1), blk>>>(wg1, w0, nullptr, Wg1, 256, 512, 512, 0, 0);
    fold_bias<<<8, blk>>>(wqkv, wg1, bg1, b0);

    // bf16 hi/lo splits
    split_kernel<<<65536, blk>>>(x, Xh, Xl, 16777216);
    split_kernel<<<3072, blk>>>(Wqkv, Wqh, Wql, 786432);
    split_kernel<<<512, blk>>>(Wg1, Wgh, Wgl, 131072);

    // wmma bf16x3 GEMMs (raw, bias fused downstream)
    mma_gemm<<<dim3(32, 12, 8), blk>>>(Wqh, Wql, Xh, Xl, qkvp, 1536);
    mma_gemm<<<dim3(32, 2, 8),  blk>>>(Wgh, Wgl, Xh, Xl, g1, 256);

    // depthwise 3x3 SAME with fused qkv bias
    dwconv_kernel<<<8 * 1536, blk>>>(qkvp, wdw, bqkv, qkvb);

    // dynamic_k (gate bias+relu fused)
    gate_dot<<<128, blk>>>(g1, wg2, bg1f, bg2);
    gate_fin<<<1, 32>>>();

    // inverse L2 norms
    norm_kernel<<<8192, blk>>>(qkvb);

    // attention
    qk_gemm<<<dim3(8, 64), blk>>>(qkvb);
    topk_softmax<<<64, blk>>>(temp);
    av_gemm<<<dim3(8, 64), blk>>>(qkvb, a1, a2, a3, a4, out);
}

// round 5
// speedup vs baseline: 1.8628x; 1.0953x over previous
#include <cuda_runtime.h>
#include <cuda_bf16.h>
#include <mma.h>
#include <math.h>
#include <cstdint>

using namespace nvcuda;

// ---------------- scratch (static device globals; no allocations) ----------
__device__ float g_Wqkv[786432];     // [1536,512]  wqkv@w0 (fp32 fold)
__device__ float g_Wg1[131072];      // [256,512]   wg1@w0  (fp32 fold)
__device__ float g_bqkv[1536];       // wqkv@b0
__device__ float g_bg1[256];         // bg1 + wg1@b0
__device__ __nv_bfloat16 g_Wqkv_hi[786432];
__device__ __nv_bfloat16 g_Wqkv_lo[786432];
__device__ __nv_bfloat16 g_Wg1_hi[131072];
__device__ __nv_bfloat16 g_Wg1_lo[131072];
__device__ __nv_bfloat16 g_Xhi[16777216];  // [8,512,4096]
__device__ __nv_bfloat16 g_Xlo[16777216];
__device__ float g_qkvp[50331648];   // [8,1536,4096] pre-depthwise qkv (no bias)
__device__ float g_qkv[50331648];    // [8,1536,4096] post-depthwise qkv
__device__ float g_g1[8388608];      // [8,256,4096]  raw gate conv1 (no bias/relu)
__device__ float g_ss[12288];        // [8,1536] per-row sum of squares (post dw)
__device__ float g_partial[128];
__device__ float g_qinv[4096];
__device__ float g_kinv[4096];
__device__ float g_Spart[2097152];   // [8 chunk][64 bh][64][64]
__device__ float g_P[262144];        // [64 bh][64][64]
__device__ int   g_dk;

// ============ wmma bf16x3 GEMM: C = W @ X =====================================
// acc = Whi*Xhi + Wlo*Xhi + Whi*Xlo. Phase 1 (it 0..15): B=Xhi chunk shared by
// Whi and Wlo MMAs. Phase 2 (it 16..31): B=Xlo, A=Whi only.
// CTA tile 128(M) x 256(N); 8 warps @ 64x64; BK=32. Raw fp32 out.
static constexpr int LDA = 40;    // As row stride (bf16), 32+8 pad
static constexpr int LDB = 264;   // Bs row stride (bf16), 256+8 pad
static constexpr uint32_t ASZ = 128 * LDA;          // elems per (buf,hl)
static constexpr uint32_t BSZ = 32 * LDB;           // elems per buf
static constexpr uint32_t GEMM_SMEM = (4 * ASZ + 2 * BSZ) * 2;  // bytes = 74752

__global__ void __launch_bounds__(256) mma_gemm(
    const __nv_bfloat16* __restrict__ Whi, const __nv_bfloat16* __restrict__ Wlo,
    const __nv_bfloat16* __restrict__ Xhi, const __nv_bfloat16* __restrict__ Xlo,
    float* __restrict__ C, int Mtotal)
{
    extern __shared__ __nv_bfloat16 sm[];
    __nv_bfloat16* As = sm;              // [2 buf][2 hl][ASZ]
    __nv_bfloat16* Bs = sm + 4 * ASZ;    // [2 buf][BSZ]

    const int tid = threadIdx.x;
    const int wid = tid >> 5;
    const int wm = wid >> 2;          // 0..1 -> rows wm*64
    const int wn = wid & 3;           // 0..3 -> cols wn*64

    const int n0 = blockIdx.x << 8;
    const int bm = blockIdx.y << 7;
    const int batch = blockIdx.z;

    const __nv_bfloat16* Ahi = Whi + (size_t)bm * 512;
    const __nv_bfloat16* Alo = Wlo + (size_t)bm * 512;
    const __nv_bfloat16* Xb_hi = Xhi + (size_t)batch * 512 * 4096 + n0;
    const __nv_bfloat16* Xb_lo = Xlo + (size_t)batch * 512 * 4096 + n0;

    const int arow = tid >> 2, aq = (tid & 3) * 8;   // A: 64 rows/pass, 2 passes
    const int brow = tid >> 5, bq = (tid & 31) * 8;  // B: 8 rows/pass, 4 passes

    wmma::fragment<wmma::accumulator, 16, 16, 16, float> acc[4][4];
    #pragma unroll
    for (int i = 0; i < 4; i++)
        #pragma unroll
        for (int j = 0; j < 4; j++) wmma::fill_fragment(acc[i][j], 0.f);

    uint4 ra[4], rb[4];
    auto loadRegs = [&](int it) {
        const int kk = (it & 15) << 5;
        if (it < 16) {
            ra[0] = *reinterpret_cast<const uint4*>(Ahi + (size_t)arow * 512 + kk + aq);
            ra[1] = *reinterpret_cast<const uint4*>(Ahi + (size_t)(arow + 64) * 512 + kk + aq);
            ra[2] = *reinterpret_cast<const uint4*>(Alo + (size_t)arow * 512 + kk + aq);
            ra[3] = *reinterpret_cast<const uint4*>(Alo + (size_t)(arow + 64) * 512 + kk + aq);
        } else {
            ra[0] = *reinterpret_cast<const uint4*>(Ahi + (size_t)arow * 512 + kk + aq);
            ra[1] = *reinterpret_cast<const uint4*>(Ahi + (size_t)(arow + 64) * 512 + kk + aq);
        }
        const __nv_bfloat16* Bseg = (it < 16) ? Xb_hi : Xb_lo;
        #pragma unroll
        for (int p = 0; p < 4; p++)
            rb[p] = *reinterpret_cast<const uint4*>(
                Bseg + (size_t)(kk + brow + p * 8) * 4096 + bq);
    };
    auto storeRegs = [&](int buf, bool dual) {
        __nv_bfloat16* A0 = As + (size_t)buf * 2 * ASZ;
        *reinterpret_cast<uint4*>(&A0[arow * LDA + aq]) = ra[0];
        *reinterpret_cast<uint4*>(&A0[(arow + 64) * LDA + aq]) = ra[1];
        if (dual) {
            __nv_bfloat16* A1 = A0 + ASZ;
            *reinterpret_cast<uint4*>(&A1[arow * LDA + aq]) = ra[2];
            *reinterpret_cast<uint4*>(&A1[(arow + 64) * LDA + aq]) = ra[3];
        }
        __nv_bfloat16* B0 = Bs + (size_t)buf * BSZ;
        #pragma unroll
        for (int p = 0; p < 4; p++)
            *reinterpret_cast<uint4*>(&B0[(brow + p * 8) * LDB + bq]) = rb[p];
    };

    loadRegs(0);
    storeRegs(0, true);
    __syncthreads();

    int buf = 0;
    for (int it = 0; it < 32; it++) {
        const bool more = (it + 1) < 32;
        if (more) loadRegs(it + 1);
        const bool dual = it < 16;

        const __nv_bfloat16* A0 = As + (size_t)buf * 2 * ASZ;
        const __nv_bfloat16* B0 = Bs + (size_t)buf * BSZ;
        #pragma unroll
        for (int ks = 0; ks < 2; ks++) {
            wmma::fragment<wmma::matrix_b, 16, 16, 16, __nv_bfloat16, wmma::row_major> bf[4];
            #pragma unroll
            for (int ni = 0; ni < 4; ni++)
                wmma::load_matrix_sync(bf[ni],
                    &B0[(ks * 16) * LDB + wn * 64 + ni * 16], LDB);
            wmma::fragment<wmma::matrix_a, 16, 16, 16, __nv_bfloat16, wmma::row_major> af[4];
            #pragma unroll
            for (int mi = 0; mi < 4; mi++)
                wmma::load_matrix_sync(af[mi],
                    &A0[(wm * 64 + mi * 16) * LDA + ks * 16], LDA);
            #pragma unroll
            for (int mi = 0; mi < 4; mi++)
                #pragma unroll
                for (int ni = 0; ni < 4; ni++)
                    wmma::mma_sync(acc[mi][ni], af[mi], bf[ni], acc[mi][ni]);
            if (dual) {
                #pragma unroll
                for (int mi = 0; mi < 4; mi++)
                    wmma::load_matrix_sync(af[mi],
                        &A0[ASZ + (wm * 64 + mi * 16) * LDA + ks * 16], LDA);
                #pragma unroll
                for (int mi = 0; mi < 4; mi++)
                    #pragma unroll
                    for (int ni = 0; ni < 4; ni++)
                        wmma::mma_sync(acc[mi][ni], af[mi], bf[ni], acc[mi][ni]);
            }
        }
        if (more) {
            storeRegs(buf ^ 1, (it + 1) < 16);
            __syncthreads();
            buf ^= 1;
        }
    }

    float* Cb = C + (size_t)batch * Mtotal * 4096;
    #pragma unroll
    for (int mi = 0; mi < 4; mi++)
        #pragma unroll
        for (int ni = 0; ni < 4; ni++)
            wmma::store_matrix_sync(
                Cb + (size_t)(bm + wm * 64 + mi * 16) * 4096 + n0 + wn * 64 + ni * 16,
                acc[mi][ni], 4096, wmma::mem_row_major);
}

// ---------------- vectorized split fp32 -> bf16 hi/lo ------------------------
__device__ __forceinline__ uint32_t pack2(float a, float b) {
    __nv_bfloat162 t = __floats2bfloat162_rn(a, b);
    return *reinterpret_cast<uint32_t*>(&t);
}
__global__ void split4_kernel(const float4* __restrict__ in,
                              uint2* __restrict__ hi,
                              uint2* __restrict__ lo, int n4)
{
    int i = blockIdx.x * 256 + threadIdx.x;
    if (i < n4) {
        float4 v = in[i];
        float h0 = __bfloat162float(__float2bfloat16(v.x));
        float h1 = __bfloat162float(__float2bfloat16(v.y));
        float h2 = __bfloat162float(__float2bfloat16(v.z));
        float h3 = __bfloat162float(__float2bfloat16(v.w));
        hi[i] = make_uint2(pack2(h0, h1), pack2(h2, h3));
        lo[i] = make_uint2(pack2(v.x - h0, v.y - h1), pack2(v.z - h2, v.w - h3));
    }
}

// ---------------- fp32 fold GEMM (small; weight folding only) ---------------
__global__ void __launch_bounds__(256) sgemm_db(
    const float* __restrict__ A, const float* __restrict__ Bm,
    float* __restrict__ C, int M, int N, int K)
{
    constexpr int BM = 128, BN = 128, BK = 16;
    __shared__ float As[2][BK][BM];
    __shared__ float Bs[2][BK][BN];

    const int bm = blockIdx.y * BM;
    const int bn = blockIdx.x * BN;
    const int tid = threadIdx.x;
    const int tx = tid & 15;
    const int ty = tid >> 4;

    const int arow = tid >> 2;
    const int ac4  = (tid & 3) * 4;
    const int brow = tid >> 5;
    const int bc4  = (tid & 31) * 4;

    float4 ra0, ra1, rb0, rb1;
    ra0 = *reinterpret_cast<const float4*>(A + (size_t)(bm + arow) * K + ac4);
    ra1 = *reinterpret_cast<const float4*>(A + (size_t)(bm + arow + 64) * K + ac4);
    rb0 = *reinterpret_cast<const float4*>(Bm + (size_t)(brow) * N + bn + bc4);
    rb1 = *reinterpret_cast<const float4*>(Bm + (size_t)(brow + 8) * N + bn + bc4);
    As[0][ac4 + 0][arow] = ra0.x; As[0][ac4 + 1][arow] = ra0.y;
    As[0][ac4 + 2][arow] = ra0.z; As[0][ac4 + 3][arow] = ra0.w;
    As[0][ac4 + 0][arow + 64] = ra1.x; As[0][ac4 + 1][arow + 64] = ra1.y;
    As[0][ac4 + 2][arow + 64] = ra1.z; As[0][ac4 + 3][arow + 64] = ra1.w;
    *reinterpret_cast<float4*>(&Bs[0][brow][bc4]) = rb0;
    *reinterpret_cast<float4*>(&Bs[0][brow + 8][bc4]) = rb1;
    __syncthreads();

    float acc[8][8] = {};
    int buf = 0;
    for (int k0 = 0; k0 < K; k0 += BK) {
        const bool more = (k0 + BK) < K;
        if (more) {
            int kn = k0 + BK;
            ra0 = *reinterpret_cast<const float4*>(A + (size_t)(bm + arow) * K + kn + ac4);
            ra1 = *reinterpret_cast<const float4*>(A + (size_t)(bm + arow + 64) * K + kn + ac4);
            rb0 = *reinterpret_cast<const float4*>(Bm + (size_t)(kn + brow) * N + bn + bc4);
            rb1 = *reinterpret_cast<const float4*>(Bm + (size_t)(kn + brow + 8) * N + bn + bc4);
        }
        #pragma unroll
        for (int kk = 0; kk < BK; kk++) {
            float4 a0 = *reinterpret_cast<const float4*>(&As[buf][kk][ty * 8]);
            float4 a1 = *reinterpret_cast<const float4*>(&As[buf][kk][ty * 8 + 4]);
            float4 b0 = *reinterpret_cast<const float4*>(&Bs[buf][kk][tx * 8]);
            float4 b1 = *reinterpret_cast<const float4*>(&Bs[buf][kk][tx * 8 + 4]);
            float ar[8] = {a0.x, a0.y, a0.z, a0.w, a1.x, a1.y, a1.z, a1.w};
            float br[8] = {b0.x, b0.y, b0.z, b0.w, b1.x, b1.y, b1.z, b1.w};
            #pragma unroll
            for (int i = 0; i < 8; i++)
                #pragma unroll
                for (int j = 0; j < 8; j++)
                    acc[i][j] = fmaf(ar[i], br[j], acc[i][j]);
        }
        if (more) {
            int nb = buf ^ 1;
            As[nb][ac4 + 0][arow] = ra0.x; As[nb][ac4 + 1][arow] = ra0.y;
            As[nb][ac4 + 2][arow] = ra0.z; As[nb][ac4 + 3][arow] = ra0.w;
            As[nb][ac4 + 0][arow + 64] = ra1.x; As[nb][ac4 + 1][arow + 64] = ra1.y;
            As[nb][ac4 + 2][arow + 64] = ra1.z; As[nb][ac4 + 3][arow + 64] = ra1.w;
            *reinterpret_cast<float4*>(&Bs[nb][brow][bc4]) = rb0;
            *reinterpret_cast<float4*>(&Bs[nb][brow + 8][bc4]) = rb1;
            __syncthreads();
            buf = nb;
        }
    }
    #pragma unroll
    for (int i = 0; i < 8; i++) {
        int m = bm + ty * 8 + i;
        #pragma unroll
        for (int j = 0; j < 8; j += 4) {
            float4 v;
            v.x = acc[i][j + 0]; v.y = acc[i][j + 1];
            v.z = acc[i][j + 2]; v.w = acc[i][j + 3];
            *reinterpret_cast<float4*>(C + (size_t)m * N + bn + tx * 8 + j) = v;
        }
    }
}

// ---------------- fold biases -----------------------------------------------
__global__ void fold_bias(const float* __restrict__ wqkv,
                          const float* __restrict__ wg1,
                          const float* __restrict__ bg1,
                          const float* __restrict__ b0)
{
    int i = blockIdx.x * 256 + threadIdx.x;
    if (i < 1536) {
        float s = 0.f;
        for (int k = 0; k < 512; k++) s = fmaf(wqkv[(size_t)i * 512 + k], b0[k], s);
        g_bqkv[i] = s;
    } else if (i < 1536 + 256) {
        int j = i - 1536;
        float s = bg1[j];
        for (int k = 0; k < 512; k++) s = fmaf(wg1[(size_t)j * 512 + k], b0[k], s);
        g_bg1[j] = s;
    }
}

// ------- depthwise 3x3 SAME, bias fused at load, sumsq reduction fused ------
__global__ void __launch_bounds__(256) dwconv_kernel(
    const float* __restrict__ inp, const float* __restrict__ w,
    const float* __restrict__ bias, float* __restrict__ outp)
{
    const int bc = blockIdx.x;
    const int ch = bc % 1536;
    const float* ip = inp + (size_t)bc * 4096;
    float*       op = outp + (size_t)bc * 4096;
    __shared__ float sh[66 * 66];
    __shared__ float red[256];
    const int tid = threadIdx.x;
    const float bv = bias[ch];
    for (int i = tid; i < 66 * 66; i += 256) {
        int r = i / 66 - 1;
        int c = i % 66 - 1;
        sh[i] = (r >= 0 && r < 64 && c >= 0 && c < 64) ? ip[r * 64 + c] + bv : 0.f;
    }
    const float* wp = w + (size_t)ch * 9;
    float w0 = wp[0], w1 = wp[1], w2 = wp[2];
    float w3 = wp[3], w4 = wp[4], w5 = wp[5];
    float w6 = wp[6], w7 = wp[7], w8 = wp[8];
    __syncthreads();
    float ss = 0.f;
    #pragma unroll
    for (int j = 0; j < 16; j++) {
        int p = tid + j * 256;
        int y = p >> 6, x = p & 63;
        const float* s0 = &sh[y * 66 + x];
        float o = s0[0]   * w0 + s0[1]   * w1 + s0[2]   * w2
                + s0[66]  * w3 + s0[67]  * w4 + s0[68]  * w5
                + s0[132] * w6 + s0[133] * w7 + s0[134] * w8;
        op[p] = o;
        ss = fmaf(o, o, ss);
    }
    red[tid] = ss;
    __syncthreads();
    for (int st = 128; st > 0; st >>= 1) {
        if (tid < st) red[tid] += red[tid + st];
        __syncthreads();
    }
    if (tid == 0) g_ss[bc] = red[0];
}

// ---------------- inverse norms from fused sumsq -----------------------------
__global__ void inv_norm()
{
    int i = blockIdx.x * 256 + threadIdx.x;   // 0..8191
    if (i < 8192) {
        int qk = i >> 12;
        int rr = i & 4095;
        int b = rr >> 9, hc = rr & 511;
        float ss = g_ss[b * 1536 + qk * 512 + hc];
        float inv = 1.f / fmaxf(sqrtf(ss), 1e-12f);
        (qk ? g_kinv : g_qinv)[rr] = inv;
    }
}

// ---------------- gate: bias+relu fused, sigmoid dot, partial sums ----------
__global__ void __launch_bounds__(256) gate_dot(
    const float* __restrict__ g1, const float* __restrict__ wg2,
    const float* __restrict__ bg1f, const float* __restrict__ bg2)
{
    __shared__ float ws[256];
    __shared__ float bs[256];
    __shared__ float red[256];
    const int tid = threadIdx.x;
    ws[tid] = wg2[tid];
    bs[tid] = bg1f[tid];
    __syncthreads();
    const int P = blockIdx.x * 256 + tid;
    const int b = P >> 12;
    const int p = P & 4095;
    const float* base = g1 + (size_t)b * 256 * 4096 + p;
    float acc = bg2[0];
    #pragma unroll 8
    for (int ch = 0; ch < 256; ch++)
        acc = fmaf(fmaxf(base[(size_t)ch * 4096] + bs[ch], 0.f), ws[ch], acc);
    float s = 1.f / (1.f + expf(-acc));
    red[tid] = s;
    __syncthreads();
    for (int st = 128; st > 0; st >>= 1) {
        if (tid < st) red[tid] += red[tid + st];
        __syncthreads();
    }
    if (tid == 0) g_partial[blockIdx.x] = red[0];
}

__global__ void gate_fin()
{
    if (threadIdx.x == 0 && blockIdx.x == 0) {
        float t = 0.f;
        for (int i = 0; i < 128; i++) t += g_partial[i];
        float mean = t * (1.f / 32768.f);
        int k = (int)floorf(64.f * mean);
        g_dk = max(0, min(64, k));
    }
}

// ---------------- split-K QK^T partials --------------------------------------
__global__ void __launch_bounds__(256) qk_gemm(const float* __restrict__ qkv)
{
    __shared__ float Qt[64 * 68];
    __shared__ float Kt[64 * 68];

    const int bh = blockIdx.y;
    const int b = bh >> 3, h = bh & 7;
    const float* Qg = qkv + ((size_t)b * 1536 + (size_t)h * 64) * 4096;
    const float* Kg = Qg + (size_t)512 * 4096;
    const int n_base = blockIdx.x * 512;

    const int tid = threadIdx.x;
    const int tx = tid & 15, ty = tid >> 4;

    float acc[4][4] = {};
    for (int n0 = n_base; n0 < n_base + 512; n0 += 64) {
        #pragma unroll
        for (int l = 0; l < 4; l++) {
            int f   = tid + l * 256;
            int row = f >> 4;
            int nl  = (f & 15) * 4;
            float4 q4 = *reinterpret_cast<const float4*>(Qg + (size_t)row * 4096 + n0 + nl);
            float4 k4 = *reinterpret_cast<const float4*>(Kg + (size_t)row * 4096 + n0 + nl);
            Qt[(nl + 0) * 68 + row] = q4.x; Qt[(nl + 1) * 68 + row] = q4.y;
            Qt[(nl + 2) * 68 + row] = q4.z; Qt[(nl + 3) * 68 + row] = q4.w;
            Kt[(nl + 0) * 68 + row] = k4.x; Kt[(nl + 1) * 68 + row] = k4.y;
            Kt[(nl + 2) * 68 + row] = k4.z; Kt[(nl + 3) * 68 + row] = k4.w;
        }
        __syncthreads();
        #pragma unroll 8
        for (int nn = 0; nn < 64; nn++) {
            float4 av = *reinterpret_cast<const float4*>(&Qt[nn * 68 + ty * 4]);
            float4 bv = *reinterpret_cast<const float4*>(&Kt[nn * 68 + tx * 4]);
            float ar[4] = {av.x, av.y, av.z, av.w};
            float br[4] = {bv.x, bv.y, bv.z, bv.w};
            #pragma unroll
            for (int i = 0; i < 4; i++)
                #pragma unroll
                for (int j = 0; j < 4; j++)
                    acc[i][j] = fmaf(ar[i], br[j], acc[i][j]);
        }
        __syncthreads();
    }
    float* Sp = &g_Spart[((size_t)blockIdx.x * 64 + bh) * 4096];
    #pragma unroll
    for (int i = 0; i < 4; i++) {
        float4 v;
        v.x = acc[i][0]; v.y = acc[i][1]; v.z = acc[i][2]; v.w = acc[i][3];
        *reinterpret_cast<float4*>(&Sp[(ty * 4 + i) * 64 + tx * 4]) = v;
    }
}

// ---------------- reduce + scale + top-k + softmax ---------------------------
__global__ void __launch_bounds__(256) topk_softmax(const float* __restrict__ temp)
{
    __shared__ float S[64 * 65];
    const int bh = blockIdx.x;
    const int b = bh >> 3, h = bh & 7;
    const int tid = threadIdx.x;
    const int base = b * 512 + h * 64;
    const float tmp = temp[h];

    for (int e = tid; e < 4096; e += 256) {
        float s = 0.f;
        #pragma unroll
        for (int c = 0; c < 8; c++)
            s += g_Spart[((size_t)c * 64 + bh) * 4096 + e];
        int row = e >> 6, col = e & 63;
        S[row * 65 + col] = s * g_qinv[base + row] * tmp * g_kinv[base + col];
    }
    __syncthreads();

    const int kd = g_dk;
    if (tid < 64) {
        float* row = &S[tid * 65];
        float m = -INFINITY;
        unsigned long long keep = 0ull;
        for (int i = 0; i < 64; i++) {
            float ai = row[i];
            int cnt = 0;
            for (int j = 0; j < 64; j++) {
                float aj = row[j];
                cnt += (aj > ai) ? 1 : ((aj == ai && j < i) ? 1 : 0);
            }
            if (cnt < kd) { keep |= (1ull << i); m = fmaxf(m, ai); }
        }
        float s = 0.f;
        for (int i = 0; i < 64; i++) {
            float e = ((keep >> i) & 1ull) ? expf(row[i] - m) : 0.f;
            row[i] = e;
            s += e;
        }
        float inv = (s > 0.f) ? 1.f / s : 0.f;
        for (int i = 0; i < 64; i++) row[i] *= inv;
    }
    __syncthreads();
    for (int e = tid; e < 4096; e += 256) {
        int row = e >> 6, col = e & 63;
        g_P[(size_t)bh * 4096 + e] = S[row * 65 + col];
    }
}

// ---------------- out = sc * P @ V -------------------------------------------
__global__ void __launch_bounds__(256) av_gemm(
    const float* __restrict__ qkv,
    const float* __restrict__ a1p, const float* __restrict__ a2p,
    const float* __restrict__ a3p, const float* __restrict__ a4p,
    float* __restrict__ outp)
{
    __shared__ float P[64 * 65];
    __shared__ float Vt[64 * 68];

    const int bh = blockIdx.y;
    const int b = bh >> 3, h = bh & 7;
    const float* Vg = qkv + ((size_t)b * 1536 + 1024 + (size_t)h * 64) * 4096;
    float* Og = outp + ((size_t)b * 512 + (size_t)h * 64) * 4096;
    const int n_base = blockIdx.x * 512;
    const float sc = a1p[0] + a2p[0] + a3p[0] + a4p[0];

    const int tid = threadIdx.x;
    const int tx = tid & 15, ty = tid >> 4;

    for (int e = tid; e < 4096; e += 256) {
        int row = e >> 6, col = e & 63;
        P[row * 65 + col] = g_P[(size_t)bh * 4096 + e];
    }
    __syncthreads();

    for (int n0 = n_base; n0 < n_base + 512; n0 += 64) {
        #pragma unroll
        for (int l = 0; l < 4; l++) {
            int f   = tid + l * 256;
            int row = f >> 4;
            int nl  = (f & 15) * 4;
            *reinterpret_cast<float4*>(&Vt[row * 68 + nl]) =
                *reinterpret_cast<const float4*>(Vg + (size_t)row * 4096 + n0 + nl);
        }
        __syncthreads();
        float o[4][4] = {};
        #pragma unroll 4
        for (int d = 0; d < 64; d++) {
            float s0 = P[(ty * 4 + 0) * 65 + d];
            float s1 = P[(ty * 4 + 1) * 65 + d];
            float s2 = P[(ty * 4 + 2) * 65 + d];
            float s3 = P[(ty * 4 + 3) * 65 + d];
            float4 v4 = *reinterpret_cast<const float4*>(&Vt[d * 68 + tx * 4]);
            o[0][0] = fmaf(s0, v4.x, o[0][0]); o[0][1] = fmaf(s0, v4.y, o[0][1]);
            o[0][2] = fmaf(s0, v4.z, o[0][2]); o[0][3] = fmaf(s0, v4.w, o[0][3]);
            o[1][0] = fmaf(s1, v4.x, o[1][0]); o[1][1] = fmaf(s1, v4.y, o[1][1]);
            o[1][2] = fmaf(s1, v4.z, o[1][2]); o[1][3] = fmaf(s1, v4.w, o[1][3]);
            o[2][0] = fmaf(s2, v4.x, o[2][0]); o[2][1] = fmaf(s2, v4.y, o[2][1]);
            o[2][2] = fmaf(s2, v4.z, o[2][2]); o[2][3] = fmaf(s2, v4.w, o[2][3]);
            o[3][0] = fmaf(s3, v4.x, o[3][0]); o[3][1] = fmaf(s3, v4.y, o[3][1]);
            o[3][2] = fmaf(s3, v4.z, o[3][2]); o[3][3] = fmaf(s3, v4.w, o[3][3]);
        }
        #pragma unroll
        for (int i = 0; i < 4; i++) {
            float4 w;
            w.x = o[i][0] * sc; w.y = o[i][1] * sc;
            w.z = o[i][2] * sc; w.w = o[i][3] * sc;
            *reinterpret_cast<float4*>(Og + (size_t)(ty * 4 + i) * 4096 + n0 + tx * 4) = w;
        }
        __syncthreads();
    }
}

// ---------------------------------------------------------------------------
extern "C" void kernel_launch(void* const* d_in, const int* in_sizes, int n_in,
                              void* d_out, int out_size)
{
    const float* x    = (const float*)d_in[0];
    const float* w0   = (const float*)d_in[1];
    const float* b0   = (const float*)d_in[2];
    const float* wqkv = (const float*)d_in[3];
    const float* wdw  = (const float*)d_in[4];
    const float* temp = (const float*)d_in[5];
    const float* wg1  = (const float*)d_in[6];
    const float* bg1  = (const float*)d_in[7];
    const float* wg2  = (const float*)d_in[8];
    const float* bg2  = (const float*)d_in[9];
    const float* a1   = (const float*)d_in[10];
    const float* a2   = (const float*)d_in[11];
    const float* a3   = (const float*)d_in[12];
    const float* a4   = (const float*)d_in[13];
    float* out = (float*)d_out;

    float *Wqkv, *Wg1, *bqkv, *bg1f, *qkvp, *qkvb, *g1;
    __nv_bfloat16 *Wqh, *Wql, *Wgh, *Wgl, *Xh, *Xl;
    cudaGetSymbolAddress((void**)&Wqkv, g_Wqkv);
    cudaGetSymbolAddress((void**)&Wg1,  g_Wg1);
    cudaGetSymbolAddress((void**)&bqkv, g_bqkv);
    cudaGetSymbolAddress((void**)&bg1f, g_bg1);
    cudaGetSymbolAddress((void**)&qkvp, g_qkvp);
    cudaGetSymbolAddress((void**)&qkvb, g_qkv);
    cudaGetSymbolAddress((void**)&g1,   g_g1);
    cudaGetSymbolAddress((void**)&Wqh,  g_Wqkv_hi);
    cudaGetSymbolAddress((void**)&Wql,  g_Wqkv_lo);
    cudaGetSymbolAddress((void**)&Wgh,  g_Wg1_hi);
    cudaGetSymbolAddress((void**)&Wgl,  g_Wg1_lo);
    cudaGetSymbolAddress((void**)&Xh,   g_Xhi);
    cudaGetSymbolAddress((void**)&Xl,   g_Xlo);

    cudaFuncSetAttribute(mma_gemm, cudaFuncAttributeMaxDynamicSharedMemorySize, GEMM_SMEM);

    dim3 blk(256);

    // fold weights (fp32, small)
    sgemm_db<<<dim3(4, 12), blk>>>(wqkv, w0, Wqkv, 1536, 512, 512);
    sgemm_db<<<dim3(4, 2),  blk>>>(wg1, w0, Wg1, 256, 512, 512);
    fold_bias<<<8, blk>>>(wqkv, wg1, bg1, b0);

    // bf16 hi/lo splits (vectorized)
    split4_kernel<<<16384, blk>>>((const float4*)x, (uint2*)Xh, (uint2*)Xl, 4194304);
    split4_kernel<<<768, blk>>>((const float4*)Wqkv, (uint2*)Wqh, (uint2*)Wql, 196608);
    split4_kernel<<<128, blk>>>((const float4*)Wg1, (uint2*)Wgh, (uint2*)Wgl, 32768);

    // wmma bf16x3 GEMMs (raw, bias fused downstream)
    mma_gemm<<<dim3(16, 12, 8), blk, GEMM_SMEM>>>(Wqh, Wql, Xh, Xl, qkvp, 1536);
    mma_gemm<<<dim3(16, 2, 8),  blk, GEMM_SMEM>>>(Wgh, Wgl, Xh, Xl, g1, 256);

    // depthwise 3x3 SAME with fused qkv bias + sumsq
    dwconv_kernel<<<8 * 1536, blk>>>(qkvp, wdw, bqkv, qkvb);

    // dynamic_k (gate bias+relu fused)
    gate_dot<<<128, blk>>>(g1, wg2, bg1f, bg2);
    gate_fin<<<1, 32>>>();

    // inverse L2 norms from fused sumsq
    inv_norm<<<32, blk>>>();

    // attention
    qk_gemm<<<dim3(8, 64), blk>>>(qkvb);
    topk_softmax<<<64, blk>>>(temp);
    av_gemm<<<dim3(8, 64), blk>>>(qkvb, a1, a2, a3, a4, out);
}

// round 6
// speedup vs baseline: 2.0102x; 1.0791x over previous
#include <cuda_runtime.h>
#include <cuda_bf16.h>
#include <mma.h>
#include <math.h>
#include <cstdint>

using namespace nvcuda;

// ---------------- scratch (static device globals; no allocations) ----------
__device__ float g_Wqkv[786432];     // [1536,512]  wqkv@w0 (fp32 fold)
__device__ float g_Wg1[131072];      // [256,512]   wg1@w0  (fp32 fold)
__device__ float g_bqkv[1536];       // wqkv@b0
__device__ float g_bg1[256];         // bg1 + wg1@b0
__device__ __nv_bfloat16 g_Wqkv_hi[786432];
__device__ __nv_bfloat16 g_Wqkv_lo[786432];
__device__ __nv_bfloat16 g_Wg1_hi[131072];
__device__ __nv_bfloat16 g_Wg1_lo[131072];
__device__ __nv_bfloat16 g_Xhi[16777216];  // [8,512,4096]
__device__ __nv_bfloat16 g_Xlo[16777216];
__device__ float g_qkvp[50331648];   // [8,1536,4096] pre-depthwise qkv (no bias)
__device__ float g_qkv[50331648];    // [8,1536,4096] post-depthwise qkv
__device__ float g_g1[8388608];      // [8,256,4096]  raw gate conv1 (no bias/relu)
__device__ float g_ss[12288];        // [8,1536] per-row sum of squares (post dw)
__device__ float g_partial[128];
__device__ float g_qinv[4096];
__device__ float g_kinv[4096];
__device__ float g_Spart[2097152];   // [8 chunk][64 bh][64][64]
__device__ float g_P[262144];        // [64 bh][64][64]
__device__ int   g_dk;

// ---------------- cp.async helpers ------------------------------------------
__device__ __forceinline__ uint32_t cvta_sh(const void* p) {
    return (uint32_t)__cvta_generic_to_shared(p);
}
#define CP16(dst, src) \
    asm volatile("cp.async.cg.shared.global [%0], [%1], 16;" :: "r"(dst), "l"(src))
#define CP_COMMIT() asm volatile("cp.async.commit_group;" ::: "memory")
#define CP_WAIT1()  asm volatile("cp.async.wait_group 1;" ::: "memory")
#define CP_WAIT0()  asm volatile("cp.async.wait_group 0;" ::: "memory")

// ============ wmma bf16x3 GEMM, cp.async 3-stage ==============================
// acc = Whi*Xhi + Wlo*Xhi + Whi*Xlo, per K-chunk of 32.
// CTA tile 128(M) x 256(N); 512 threads, 16 warps @ 64x32. Raw fp32 out.
static constexpr int LDA = 40;                       // A row stride (bf16)
static constexpr int LDB = 264;                      // B row stride (bf16)
static constexpr uint32_t A_T = 128 * LDA;           // elems per A tile
static constexpr uint32_t B_T = 32 * LDB;            // elems per B tile
static constexpr uint32_t STG = 2 * A_T + 2 * B_T;   // elems per stage
static constexpr uint32_t GEMM_SMEM = STG * 3 * 2;   // bytes = 162816

__global__ void __launch_bounds__(512) mma_gemm(
    const __nv_bfloat16* __restrict__ Whi, const __nv_bfloat16* __restrict__ Wlo,
    const __nv_bfloat16* __restrict__ Xhi, const __nv_bfloat16* __restrict__ Xlo,
    float* __restrict__ C, int Mtotal)
{
    extern __shared__ __nv_bfloat16 sm[];

    const int tid = threadIdx.x;
    const int wid = tid >> 5;
    const int wm = wid >> 3;          // 0..1 -> rows wm*64
    const int wn = wid & 7;           // 0..7 -> cols wn*32

    const int n0 = blockIdx.x << 8;
    const int bm = blockIdx.y << 7;
    const int batch = blockIdx.z;

    const __nv_bfloat16* Ahi = Whi + (size_t)bm * 512;
    const __nv_bfloat16* Alo = Wlo + (size_t)bm * 512;
    const __nv_bfloat16* Xb_hi = Xhi + (size_t)batch * 512 * 4096 + n0;
    const __nv_bfloat16* Xb_lo = Xlo + (size_t)batch * 512 * 4096 + n0;

    const int arow = tid >> 2, aq = (tid & 3) * 8;    // 128 rows x 4 slots
    // B: two passes of 512

    auto prefetch = [&](int c) {
        if (c < 16) {
            const int k0 = c << 5;
            __nv_bfloat16* st = sm + (size_t)(c % 3) * STG;
            CP16(cvta_sh(st + arow * LDA + aq),
                 Ahi + (size_t)arow * 512 + k0 + aq);
            CP16(cvta_sh(st + A_T + arow * LDA + aq),
                 Alo + (size_t)arow * 512 + k0 + aq);
            #pragma unroll
            for (int p = 0; p < 2; p++) {
                int idx = tid + p * 512;
                int row = idx >> 5, q = (idx & 31) * 8;
                CP16(cvta_sh(st + 2 * A_T + row * LDB + q),
                     Xb_hi + (size_t)(k0 + row) * 4096 + q);
                CP16(cvta_sh(st + 2 * A_T + B_T + row * LDB + q),
                     Xb_lo + (size_t)(k0 + row) * 4096 + q);
            }
        }
        CP_COMMIT();
    };

    wmma::fragment<wmma::accumulator, 16, 16, 16, float> acc[4][2];
    #pragma unroll
    for (int i = 0; i < 4; i++)
        #pragma unroll
        for (int j = 0; j < 2; j++) wmma::fill_fragment(acc[i][j], 0.f);

    prefetch(0);
    prefetch(1);

    for (int c = 0; c < 16; c++) {
        CP_WAIT1();
        __syncthreads();
        prefetch(c + 2);

        const __nv_bfloat16* st = sm + (size_t)(c % 3) * STG;
        const __nv_bfloat16* A0 = st;
        const __nv_bfloat16* A1 = st + A_T;
        const __nv_bfloat16* B0 = st + 2 * A_T;
        const __nv_bfloat16* B1 = st + 2 * A_T + B_T;

        #pragma unroll
        for (int ks = 0; ks < 2; ks++) {
            wmma::fragment<wmma::matrix_b, 16, 16, 16, __nv_bfloat16, wmma::row_major> bh[2];
            wmma::fragment<wmma::matrix_a, 16, 16, 16, __nv_bfloat16, wmma::row_major> ah[4];
            #pragma unroll
            for (int ni = 0; ni < 2; ni++)
                wmma::load_matrix_sync(bh[ni],
                    &B0[(ks * 16) * LDB + wn * 32 + ni * 16], LDB);
            #pragma unroll
            for (int mi = 0; mi < 4; mi++)
                wmma::load_matrix_sync(ah[mi],
                    &A0[(wm * 64 + mi * 16) * LDA + ks * 16], LDA);
            #pragma unroll
            for (int mi = 0; mi < 4; mi++)
                #pragma unroll
                for (int ni = 0; ni < 2; ni++)
                    wmma::mma_sync(acc[mi][ni], ah[mi], bh[ni], acc[mi][ni]);
            {
                wmma::fragment<wmma::matrix_a, 16, 16, 16, __nv_bfloat16, wmma::row_major> al[4];
                #pragma unroll
                for (int mi = 0; mi < 4; mi++)
                    wmma::load_matrix_sync(al[mi],
                        &A1[(wm * 64 + mi * 16) * LDA + ks * 16], LDA);
                #pragma unroll
                for (int mi = 0; mi < 4; mi++)
                    #pragma unroll
                    for (int ni = 0; ni < 2; ni++)
                        wmma::mma_sync(acc[mi][ni], al[mi], bh[ni], acc[mi][ni]);
            }
            {
                wmma::fragment<wmma::matrix_b, 16, 16, 16, __nv_bfloat16, wmma::row_major> bl[2];
                #pragma unroll
                for (int ni = 0; ni < 2; ni++)
                    wmma::load_matrix_sync(bl[ni],
                        &B1[(ks * 16) * LDB + wn * 32 + ni * 16], LDB);
                #pragma unroll
                for (int mi = 0; mi < 4; mi++)
                    #pragma unroll
                    for (int ni = 0; ni < 2; ni++)
                        wmma::mma_sync(acc[mi][ni], ah[mi], bl[ni], acc[mi][ni]);
            }
        }
    }
    CP_WAIT0();
    __syncthreads();

    float* Cb = C + (size_t)batch * Mtotal * 4096;
    #pragma unroll
    for (int mi = 0; mi < 4; mi++)
        #pragma unroll
        for (int ni = 0; ni < 2; ni++)
            wmma::store_matrix_sync(
                Cb + (size_t)(bm + wm * 64 + mi * 16) * 4096 + n0 + wn * 32 + ni * 16,
                acc[mi][ni], 4096, wmma::mem_row_major);
}

// ---------------- vectorized split fp32 -> bf16 hi/lo ------------------------
__device__ __forceinline__ uint32_t pack2(float a, float b) {
    __nv_bfloat162 t = __floats2bfloat162_rn(a, b);
    return *reinterpret_cast<uint32_t*>(&t);
}
__global__ void split4_kernel(const float4* __restrict__ in,
                              uint2* __restrict__ hi,
                              uint2* __restrict__ lo, int n4)
{
    int i = blockIdx.x * 256 + threadIdx.x;
    if (i < n4) {
        float4 v = in[i];
        float h0 = __bfloat162float(__float2bfloat16(v.x));
        float h1 = __bfloat162float(__float2bfloat16(v.y));
        float h2 = __bfloat162float(__float2bfloat16(v.z));
        float h3 = __bfloat162float(__float2bfloat16(v.w));
        hi[i] = make_uint2(pack2(h0, h1), pack2(h2, h3));
        lo[i] = make_uint2(pack2(v.x - h0, v.y - h1), pack2(v.z - h2, v.w - h3));
    }
}

// ---------------- fp32 fold GEMM (small; weight folding only) ---------------
__global__ void __launch_bounds__(256) sgemm_db(
    const float* __restrict__ A, const float* __restrict__ Bm,
    float* __restrict__ C, int M, int N, int K)
{
    constexpr int BM = 128, BN = 128, BK = 16;
    __shared__ float As[2][BK][BM];
    __shared__ float Bs[2][BK][BN];

    const int bm = blockIdx.y * BM;
    const int bn = blockIdx.x * BN;
    const int tid = threadIdx.x;
    const int tx = tid & 15;
    const int ty = tid >> 4;

    const int arow = tid >> 2;
    const int ac4  = (tid & 3) * 4;
    const int brow = tid >> 5;
    const int bc4  = (tid & 31) * 4;

    float4 ra0, ra1, rb0, rb1;
    ra0 = *reinterpret_cast<const float4*>(A + (size_t)(bm + arow) * K + ac4);
    ra1 = *reinterpret_cast<const float4*>(A + (size_t)(bm + arow + 64) * K + ac4);
    rb0 = *reinterpret_cast<const float4*>(Bm + (size_t)(brow) * N + bn + bc4);
    rb1 = *reinterpret_cast<const float4*>(Bm + (size_t)(brow + 8) * N + bn + bc4);
    As[0][ac4 + 0][arow] = ra0.x; As[0][ac4 + 1][arow] = ra0.y;
    As[0][ac4 + 2][arow] = ra0.z; As[0][ac4 + 3][arow] = ra0.w;
    As[0][ac4 + 0][arow + 64] = ra1.x; As[0][ac4 + 1][arow + 64] = ra1.y;
    As[0][ac4 + 2][arow + 64] = ra1.z; As[0][ac4 + 3][arow + 64] = ra1.w;
    *reinterpret_cast<float4*>(&Bs[0][brow][bc4]) = rb0;
    *reinterpret_cast<float4*>(&Bs[0][brow + 8][bc4]) = rb1;
    __syncthreads();

    float acc[8][8] = {};
    int buf = 0;
    for (int k0 = 0; k0 < K; k0 += BK) {
        const bool more = (k0 + BK) < K;
        if (more) {
            int kn = k0 + BK;
            ra0 = *reinterpret_cast<const float4*>(A + (size_t)(bm + arow) * K + kn + ac4);
            ra1 = *reinterpret_cast<const float4*>(A + (size_t)(bm + arow + 64) * K + kn + ac4);
            rb0 = *reinterpret_cast<const float4*>(Bm + (size_t)(kn + brow) * N + bn + bc4);
            rb1 = *reinterpret_cast<const float4*>(Bm + (size_t)(kn + brow + 8) * N + bn + bc4);
        }
        #pragma unroll
        for (int kk = 0; kk < BK; kk++) {
            float4 a0 = *reinterpret_cast<const float4*>(&As[buf][kk][ty * 8]);
            float4 a1 = *reinterpret_cast<const float4*>(&As[buf][kk][ty * 8 + 4]);
            float4 b0 = *reinterpret_cast<const float4*>(&Bs[buf][kk][tx * 8]);
            float4 b1 = *reinterpret_cast<const float4*>(&Bs[buf][kk][tx * 8 + 4]);
            float ar[8] = {a0.x, a0.y, a0.z, a0.w, a1.x, a1.y, a1.z, a1.w};
            float br[8] = {b0.x, b0.y, b0.z, b0.w, b1.x, b1.y, b1.z, b1.w};
            #pragma unroll
            for (int i = 0; i < 8; i++)
                #pragma unroll
                for (int j = 0; j < 8; j++)
                    acc[i][j] = fmaf(ar[i], br[j], acc[i][j]);
        }
        if (more) {
            int nb = buf ^ 1;
            As[nb][ac4 + 0][arow] = ra0.x; As[nb][ac4 + 1][arow] = ra0.y;
            As[nb][ac4 + 2][arow] = ra0.z; As[nb][ac4 + 3][arow] = ra0.w;
            As[nb][ac4 + 0][arow + 64] = ra1.x; As[nb][ac4 + 1][arow + 64] = ra1.y;
            As[nb][ac4 + 2][arow + 64] = ra1.z; As[nb][ac4 + 3][arow + 64] = ra1.w;
            *reinterpret_cast<float4*>(&Bs[nb][brow][bc4]) = rb0;
            *reinterpret_cast<float4*>(&Bs[nb][brow + 8][bc4]) = rb1;
            __syncthreads();
            buf = nb;
        }
    }
    #pragma unroll
    for (int i = 0; i < 8; i++) {
        int m = bm + ty * 8 + i;
        #pragma unroll
        for (int j = 0; j < 8; j += 4) {
            float4 v;
            v.x = acc[i][j + 0]; v.y = acc[i][j + 1];
            v.z = acc[i][j + 2]; v.w = acc[i][j + 3];
            *reinterpret_cast<float4*>(C + (size_t)m * N + bn + tx * 8 + j) = v;
        }
    }
}

// ---------------- fold biases -----------------------------------------------
__global__ void fold_bias(const float* __restrict__ wqkv,
                          const float* __restrict__ wg1,
                          const float* __restrict__ bg1,
                          const float* __restrict__ b0)
{
    int i = blockIdx.x * 256 + threadIdx.x;
    if (i < 1536) {
        float s = 0.f;
        for (int k = 0; k < 512; k++) s = fmaf(wqkv[(size_t)i * 512 + k], b0[k], s);
        g_bqkv[i] = s;
    } else if (i < 1536 + 256) {
        int j = i - 1536;
        float s = bg1[j];
        for (int k = 0; k < 512; k++) s = fmaf(wg1[(size_t)j * 512 + k], b0[k], s);
        g_bg1[j] = s;
    }
}

// ------- depthwise 3x3 SAME, bias fused at load, sumsq reduction fused ------
__global__ void __launch_bounds__(256) dwconv_kernel(
    const float* __restrict__ inp, const float* __restrict__ w,
    const float* __restrict__ bias, float* __restrict__ outp)
{
    const int bc = blockIdx.x;
    const int ch = bc % 1536;
    const float* ip = inp + (size_t)bc * 4096;
    float*       op = outp + (size_t)bc * 4096;
    __shared__ float sh[66 * 66];
    __shared__ float red[256];
    const int tid = threadIdx.x;
    const float bv = bias[ch];
    for (int i = tid; i < 66 * 66; i += 256) {
        int r = i / 66 - 1;
        int c = i % 66 - 1;
        sh[i] = (r >= 0 && r < 64 && c >= 0 && c < 64) ? ip[r * 64 + c] + bv : 0.f;
    }
    const float* wp = w + (size_t)ch * 9;
    float w0 = wp[0], w1 = wp[1], w2 = wp[2];
    float w3 = wp[3], w4 = wp[4], w5 = wp[5];
    float w6 = wp[6], w7 = wp[7], w8 = wp[8];
    __syncthreads();
    float ss = 0.f;
    #pragma unroll
    for (int j = 0; j < 16; j++) {
        int p = tid + j * 256;
        int y = p >> 6, x = p & 63;
        const float* s0 = &sh[y * 66 + x];
        float o = s0[0]   * w0 + s0[1]   * w1 + s0[2]   * w2
                + s0[66]  * w3 + s0[67]  * w4 + s0[68]  * w5
                + s0[132] * w6 + s0[133] * w7 + s0[134] * w8;
        op[p] = o;
        ss = fmaf(o, o, ss);
    }
    red[tid] = ss;
    __syncthreads();
    for (int st = 128; st > 0; st >>= 1) {
        if (tid < st) red[tid] += red[tid + st];
        __syncthreads();
    }
    if (tid == 0) g_ss[bc] = red[0];
}

// ---------------- inverse norms from fused sumsq -----------------------------
__global__ void inv_norm()
{
    int i = blockIdx.x * 256 + threadIdx.x;   // 0..8191
    if (i < 8192) {
        int qk = i >> 12;
        int rr = i & 4095;
        int b = rr >> 9, hc = rr & 511;
        float ss = g_ss[b * 1536 + qk * 512 + hc];
        float inv = 1.f / fmaxf(sqrtf(ss), 1e-12f);
        (qk ? g_kinv : g_qinv)[rr] = inv;
    }
}

// ---------------- gate: bias+relu fused, sigmoid dot, partial sums ----------
__global__ void __launch_bounds__(256) gate_dot(
    const float* __restrict__ g1, const float* __restrict__ wg2,
    const float* __restrict__ bg1f, const float* __restrict__ bg2)
{
    __shared__ float ws[256];
    __shared__ float bs[256];
    __shared__ float red[256];
    const int tid = threadIdx.x;
    ws[tid] = wg2[tid];
    bs[tid] = bg1f[tid];
    __syncthreads();
    const int P = blockIdx.x * 256 + tid;
    const int b = P >> 12;
    const int p = P & 4095;
    const float* base = g1 + (size_t)b * 256 * 4096 + p;
    float acc = bg2[0];
    #pragma unroll 8
    for (int ch = 0; ch < 256; ch++)
        acc = fmaf(fmaxf(base[(size_t)ch * 4096] + bs[ch], 0.f), ws[ch], acc);
    float s = 1.f / (1.f + expf(-acc));
    red[tid] = s;
    __syncthreads();
    for (int st = 128; st > 0; st >>= 1) {
        if (tid < st) red[tid] += red[tid + st];
        __syncthreads();
    }
    if (tid == 0) g_partial[blockIdx.x] = red[0];
}

__global__ void gate_fin()
{
    if (threadIdx.x == 0 && blockIdx.x == 0) {
        float t = 0.f;
        for (int i = 0; i < 128; i++) t += g_partial[i];
        float mean = t * (1.f / 32768.f);
        int k = (int)floorf(64.f * mean);
        g_dk = max(0, min(64, k));
    }
}

// ---------------- split-K QK^T partials --------------------------------------
__global__ void __launch_bounds__(256) qk_gemm(const float* __restrict__ qkv)
{
    __shared__ float Qt[64 * 68];
    __shared__ float Kt[64 * 68];

    const int bh = blockIdx.y;
    const int b = bh >> 3, h = bh & 7;
    const float* Qg = qkv + ((size_t)b * 1536 + (size_t)h * 64) * 4096;
    const float* Kg = Qg + (size_t)512 * 4096;
    const int n_base = blockIdx.x * 512;

    const int tid = threadIdx.x;
    const int tx = tid & 15, ty = tid >> 4;

    float acc[4][4] = {};
    for (int n0 = n_base; n0 < n_base + 512; n0 += 64) {
        #pragma unroll
        for (int l = 0; l < 4; l++) {
            int f   = tid + l * 256;
            int row = f >> 4;
            int nl  = (f & 15) * 4;
            float4 q4 = *reinterpret_cast<const float4*>(Qg + (size_t)row * 4096 + n0 + nl);
            float4 k4 = *reinterpret_cast<const float4*>(Kg + (size_t)row * 4096 + n0 + nl);
            Qt[(nl + 0) * 68 + row] = q4.x; Qt[(nl + 1) * 68 + row] = q4.y;
            Qt[(nl + 2) * 68 + row] = q4.z; Qt[(nl + 3) * 68 + row] = q4.w;
            Kt[(nl + 0) * 68 + row] = k4.x; Kt[(nl + 1) * 68 + row] = k4.y;
            Kt[(nl + 2) * 68 + row] = k4.z; Kt[(nl + 3) * 68 + row] = k4.w;
        }
        __syncthreads();
        #pragma unroll 8
        for (int nn = 0; nn < 64; nn++) {
            float4 av = *reinterpret_cast<const float4*>(&Qt[nn * 68 + ty * 4]);
            float4 bv = *reinterpret_cast<const float4*>(&Kt[nn * 68 + tx * 4]);
            float ar[4] = {av.x, av.y, av.z, av.w};
            float br[4] = {bv.x, bv.y, bv.z, bv.w};
            #pragma unroll
            for (int i = 0; i < 4; i++)
                #pragma unroll
                for (int j = 0; j < 4; j++)
                    acc[i][j] = fmaf(ar[i], br[j], acc[i][j]);
        }
        __syncthreads();
    }
    float* Sp = &g_Spart[((size_t)blockIdx.x * 64 + bh) * 4096];
    #pragma unroll
    for (int i = 0; i < 4; i++) {
        float4 v;
        v.x = acc[i][0]; v.y = acc[i][1]; v.z = acc[i][2]; v.w = acc[i][3];
        *reinterpret_cast<float4*>(&Sp[(ty * 4 + i) * 64 + tx * 4]) = v;
    }
}

// ---------------- reduce + scale + top-k + softmax ---------------------------
__global__ void __launch_bounds__(256) topk_softmax(const float* __restrict__ temp)
{
    __shared__ float S[64 * 65];
    const int bh = blockIdx.x;
    const int b = bh >> 3, h = bh & 7;
    const int tid = threadIdx.x;
    const int base = b * 512 + h * 64;
    const float tmp = temp[h];

    for (int e = tid; e < 4096; e += 256) {
        float s = 0.f;
        #pragma unroll
        for (int c = 0; c < 8; c++)
            s += g_Spart[((size_t)c * 64 + bh) * 4096 + e];
        int row = e >> 6, col = e & 63;
        S[row * 65 + col] = s * g_qinv[base + row] * tmp * g_kinv[base + col];
    }
    __syncthreads();

    const int kd = g_dk;
    if (tid < 64) {
        float* row = &S[tid * 65];
        float m = -INFINITY;
        unsigned long long keep = 0ull;
        for (int i = 0; i < 64; i++) {
            float ai = row[i];
            int cnt = 0;
            for (int j = 0; j < 64; j++) {
                float aj = row[j];
                cnt += (aj > ai) ? 1 : ((aj == ai && j < i) ? 1 : 0);
            }
            if (cnt < kd) { keep |= (1ull << i); m = fmaxf(m, ai); }
        }
        float s = 0.f;
        for (int i = 0; i < 64; i++) {
            float e = ((keep >> i) & 1ull) ? expf(row[i] - m) : 0.f;
            row[i] = e;
            s += e;
        }
        float inv = (s > 0.f) ? 1.f / s : 0.f;
        for (int i = 0; i < 64; i++) row[i] *= inv;
    }
    __syncthreads();
    for (int e = tid; e < 4096; e += 256) {
        int row = e >> 6, col = e & 63;
        g_P[(size_t)bh * 4096 + e] = S[row * 65 + col];
    }
}

// ---------------- out = sc * P @ V -------------------------------------------
__global__ void __launch_bounds__(256) av_gemm(
    const float* __restrict__ qkv,
    const float* __restrict__ a1p, const float* __restrict__ a2p,
    const float* __restrict__ a3p, const float* __restrict__ a4p,
    float* __restrict__ outp)
{
    __shared__ float P[64 * 65];
    __shared__ float Vt[64 * 68];

    const int bh = blockIdx.y;
    const int b = bh >> 3, h = bh & 7;
    const float* Vg = qkv + ((size_t)b * 1536 + 1024 + (size_t)h * 64) * 4096;
    float* Og = outp + ((size_t)b * 512 + (size_t)h * 64) * 4096;
    const int n_base = blockIdx.x * 512;
    const float sc = a1p[0] + a2p[0] + a3p[0] + a4p[0];

    const int tid = threadIdx.x;
    const int tx = tid & 15, ty = tid >> 4;

    for (int e = tid; e < 4096; e += 256) {
        int row = e >> 6, col = e & 63;
        P[row * 65 + col] = g_P[(size_t)bh * 4096 + e];
    }
    __syncthreads();

    for (int n0 = n_base; n0 < n_base + 512; n0 += 64) {
        #pragma unroll
        for (int l = 0; l < 4; l++) {
            int f   = tid + l * 256;
            int row = f >> 4;
            int nl  = (f & 15) * 4;
            *reinterpret_cast<float4*>(&Vt[row * 68 + nl]) =
                *reinterpret_cast<const float4*>(Vg + (size_t)row * 4096 + n0 + nl);
        }
        __syncthreads();
        float o[4][4] = {};
        #pragma unroll 4
        for (int d = 0; d < 64; d++) {
            float s0 = P[(ty * 4 + 0) * 65 + d];
            float s1 = P[(ty * 4 + 1) * 65 + d];
            float s2 = P[(ty * 4 + 2) * 65 + d];
            float s3 = P[(ty * 4 + 3) * 65 + d];
            float4 v4 = *reinterpret_cast<const float4*>(&Vt[d * 68 + tx * 4]);
            o[0][0] = fmaf(s0, v4.x, o[0][0]); o[0][1] = fmaf(s0, v4.y, o[0][1]);
            o[0][2] = fmaf(s0, v4.z, o[0][2]); o[0][3] = fmaf(s0, v4.w, o[0][3]);
            o[1][0] = fmaf(s1, v4.x, o[1][0]); o[1][1] = fmaf(s1, v4.y, o[1][1]);
            o[1][2] = fmaf(s1, v4.z, o[1][2]); o[1][3] = fmaf(s1, v4.w, o[1][3]);
            o[2][0] = fmaf(s2, v4.x, o[2][0]); o[2][1] = fmaf(s2, v4.y, o[2][1]);
            o[2][2] = fmaf(s2, v4.z, o[2][2]); o[2][3] = fmaf(s2, v4.w, o[2][3]);
            o[3][0] = fmaf(s3, v4.x, o[3][0]); o[3][1] = fmaf(s3, v4.y, o[3][1]);
            o[3][2] = fmaf(s3, v4.z, o[3][2]); o[3][3] = fmaf(s3, v4.w, o[3][3]);
        }
        #pragma unroll
        for (int i = 0; i < 4; i++) {
            float4 w;
            w.x = o[i][0] * sc; w.y = o[i][1] * sc;
            w.z = o[i][2] * sc; w.w = o[i][3] * sc;
            *reinterpret_cast<float4*>(Og + (size_t)(ty * 4 + i) * 4096 + n0 + tx * 4) = w;
        }
        __syncthreads();
    }
}

// ---------------------------------------------------------------------------
extern "C" void kernel_launch(void* const* d_in, const int* in_sizes, int n_in,
                              void* d_out, int out_size)
{
    const float* x    = (const float*)d_in[0];
    const float* w0   = (const float*)d_in[1];
    const float* b0   = (const float*)d_in[2];
    const float* wqkv = (const float*)d_in[3];
    const float* wdw  = (const float*)d_in[4];
    const float* temp = (const float*)d_in[5];
    const float* wg1  = (const float*)d_in[6];
    const float* bg1  = (const float*)d_in[7];
    const float* wg2  = (const float*)d_in[8];
    const float* bg2  = (const float*)d_in[9];
    const float* a1   = (const float*)d_in[10];
    const float* a2   = (const float*)d_in[11];
    const float* a3   = (const float*)d_in[12];
    const float* a4   = (const float*)d_in[13];
    float* out = (float*)d_out;

    float *Wqkv, *Wg1, *bqkv, *bg1f, *qkvp, *qkvb, *g1;
    __nv_bfloat16 *Wqh, *Wql, *Wgh, *Wgl, *Xh, *Xl;
    cudaGetSymbolAddress((void**)&Wqkv, g_Wqkv);
    cudaGetSymbolAddress((void**)&Wg1,  g_Wg1);
    cudaGetSymbolAddress((void**)&bqkv, g_bqkv);
    cudaGetSymbolAddress((void**)&bg1f, g_bg1);
    cudaGetSymbolAddress((void**)&qkvp, g_qkvp);
    cudaGetSymbolAddress((void**)&qkvb, g_qkv);
    cudaGetSymbolAddress((void**)&g1,   g_g1);
    cudaGetSymbolAddress((void**)&Wqh,  g_Wqkv_hi);
    cudaGetSymbolAddress((void**)&Wql,  g_Wqkv_lo);
    cudaGetSymbolAddress((void**)&Wgh,  g_Wg1_hi);
    cudaGetSymbolAddress((void**)&Wgl,  g_Wg1_lo);
    cudaGetSymbolAddress((void**)&Xh,   g_Xhi);
    cudaGetSymbolAddress((void**)&Xl,   g_Xlo);

    cudaFuncSetAttribute(mma_gemm, cudaFuncAttributeMaxDynamicSharedMemorySize, GEMM_SMEM);

    dim3 blk(256);

    // fold weights (fp32, small)
    sgemm_db<<<dim3(4, 12), blk>>>(wqkv, w0, Wqkv, 1536, 512, 512);
    sgemm_db<<<dim3(4, 2),  blk>>>(wg1, w0, Wg1, 256, 512, 512);
    fold_bias<<<8, blk>>>(wqkv, wg1, bg1, b0);

    // bf16 hi/lo splits (vectorized)
    split4_kernel<<<16384, blk>>>((const float4*)x, (uint2*)Xh, (uint2*)Xl, 4194304);
    split4_kernel<<<768, blk>>>((const float4*)Wqkv, (uint2*)Wqh, (uint2*)Wql, 196608);
    split4_kernel<<<128, blk>>>((const float4*)Wg1, (uint2*)Wgh, (uint2*)Wgl, 32768);

    // wmma bf16x3 GEMMs, cp.async 3-stage (raw, bias fused downstream)
    mma_gemm<<<dim3(16, 12, 8), 512, GEMM_SMEM>>>(Wqh, Wql, Xh, Xl, qkvp, 1536);
    mma_gemm<<<dim3(16, 2, 8),  512, GEMM_SMEM>>>(Wgh, Wgl, Xh, Xl, g1, 256);

    // depthwise 3x3 SAME with fused qkv bias + sumsq
    dwconv_kernel<<<8 * 1536, blk>>>(qkvp, wdw, bqkv, qkvb);

    // dynamic_k (gate bias+relu fused)
    gate_dot<<<128, blk>>>(g1, wg2, bg1f, bg2);
    gate_fin<<<1, 32>>>();

    // inverse L2 norms from fused sumsq
    inv_norm<<<32, blk>>>();

    // attention
    qk_gemm<<<dim3(8, 64), blk>>>(qkvb);
    topk_softmax<<<64, blk>>>(temp);
    av_gemm<<<dim3(8, 64), blk>>>(qkvb, a1, a2, a3, a4, out);
}

// round 7
// speedup vs baseline: 2.0987x; 1.0440x over previous
#include <cuda_runtime.h>
#include <cuda_bf16.h>
#include <mma.h>
#include <math.h>
#include <cstdint>

using namespace nvcuda;

// ---------------- scratch (static device globals; no allocations) ----------
__device__ float g_bqkv[1536];       // wqkv@b0
__device__ float g_bg1[256];         // bg1 + wg1@b0
__device__ __nv_bfloat16 g_Wqkv_hi[786432];
__device__ __nv_bfloat16 g_Wqkv_lo[786432];
__device__ __nv_bfloat16 g_Wg1_hi[131072];
__device__ __nv_bfloat16 g_Wg1_lo[131072];
__device__ __nv_bfloat16 g_Xhi[16777216];  // [8,512,4096]
__device__ __nv_bfloat16 g_Xlo[16777216];
__device__ float g_qkvp[50331648];   // [8,1536,4096] pre-depthwise qkv (no bias)
__device__ float g_qkv[50331648];    // [8,1536,4096] post-depthwise qkv
__device__ float g_g1[8388608];      // [8,256,4096]  raw gate conv1 (no bias/relu)
__device__ float g_ss[12288];        // [8,1536] per-row sum of squares (post dw)
__device__ float g_partial[128];
__device__ float g_qinv[4096];
__device__ float g_kinv[4096];
__device__ float g_Spart[2097152];   // [8 chunk][64 bh][64][64]
__device__ float g_P[262144];        // [64 bh][64][64]
__device__ int   g_dk;

// ---------------- cp.async helpers ------------------------------------------
__device__ __forceinline__ uint32_t cvta_sh(const void* p) {
    return (uint32_t)__cvta_generic_to_shared(p);
}
#define CP16(dst, src) \
    asm volatile("cp.async.cg.shared.global [%0], [%1], 16;" :: "r"(dst), "l"(src))
#define CP_COMMIT() asm volatile("cp.async.commit_group;" ::: "memory")
#define CP_WAIT1()  asm volatile("cp.async.wait_group 1;" ::: "memory")
#define CP_WAIT0()  asm volatile("cp.async.wait_group 0;" ::: "memory")

// ============ wmma bf16x3 GEMM, cp.async 3-stage, 8 warps @ 64x64 ============
// acc = Whi*Xhi + Wlo*Xhi + Whi*Xlo per K-chunk of 32.
// CTA 128(M) x 256(N); 256 threads. Raw fp32 out (bias fused downstream).
static constexpr int LDA = 40;                       // A row stride (bf16)
static constexpr int LDB = 264;                      // B row stride (bf16)
static constexpr uint32_t A_T = 128 * LDA;           // 5120
static constexpr uint32_t B_T = 32 * LDB;            // 8448
static constexpr uint32_t STG = 2 * A_T + 2 * B_T;   // 27136 elems
static constexpr uint32_t GEMM_SMEM = STG * 3 * 2;   // 162816 bytes

__global__ void __launch_bounds__(256) mma_gemm(
    const __nv_bfloat16* __restrict__ Whi, const __nv_bfloat16* __restrict__ Wlo,
    const __nv_bfloat16* __restrict__ Xhi, const __nv_bfloat16* __restrict__ Xlo,
    float* __restrict__ C, int Mtotal)
{
    extern __shared__ __nv_bfloat16 sm[];

    const int tid = threadIdx.x;
    const int wid = tid >> 5;
    const int wm = wid >> 2;          // 0..1 -> rows wm*64
    const int wn = wid & 3;           // 0..3 -> cols wn*64

    const int n0 = blockIdx.x << 8;
    const int bm = blockIdx.y << 7;
    const int batch = blockIdx.z;

    const __nv_bfloat16* Ahi = Whi + (size_t)bm * 512;
    const __nv_bfloat16* Alo = Wlo + (size_t)bm * 512;
    const __nv_bfloat16* Xb_hi = Xhi + (size_t)batch * 512 * 4096 + n0;
    const __nv_bfloat16* Xb_lo = Xlo + (size_t)batch * 512 * 4096 + n0;

    const int arow = tid >> 1, aq = (tid & 1) * 16;
    const int brow = tid >> 3, bq = (tid & 7) * 32;

    auto prefetch = [&](int c) {
        if (c < 16) {
            const int k0 = c << 5;
            __nv_bfloat16* st = sm + (size_t)(c % 3) * STG;
            CP16(cvta_sh(st + arow * LDA + aq),
                 Ahi + (size_t)arow * 512 + k0 + aq);
            CP16(cvta_sh(st + arow * LDA + aq + 8),
                 Ahi + (size_t)arow * 512 + k0 + aq + 8);
            CP16(cvta_sh(st + A_T + arow * LDA + aq),
                 Alo + (size_t)arow * 512 + k0 + aq);
            CP16(cvta_sh(st + A_T + arow * LDA + aq + 8),
                 Alo + (size_t)arow * 512 + k0 + aq + 8);
            #pragma unroll
            for (int j = 0; j < 4; j++)
                CP16(cvta_sh(st + 2 * A_T + brow * LDB + bq + j * 8),
                     Xb_hi + (size_t)(k0 + brow) * 4096 + bq + j * 8);
            #pragma unroll
            for (int j = 0; j < 4; j++)
                CP16(cvta_sh(st + 2 * A_T + B_T + brow * LDB + bq + j * 8),
                     Xb_lo + (size_t)(k0 + brow) * 4096 + bq + j * 8);
        }
        CP_COMMIT();
    };

    wmma::fragment<wmma::accumulator, 16, 16, 16, float> acc[4][4];
    #pragma unroll
    for (int i = 0; i < 4; i++)
        #pragma unroll
        for (int j = 0; j < 4; j++) wmma::fill_fragment(acc[i][j], 0.f);

    prefetch(0);
    prefetch(1);

    for (int c = 0; c < 16; c++) {
        CP_WAIT1();
        __syncthreads();
        prefetch(c + 2);

        const __nv_bfloat16* st = sm + (size_t)(c % 3) * STG;
        const __nv_bfloat16* A0 = st;
        const __nv_bfloat16* A1 = st + A_T;
        const __nv_bfloat16* B0 = st + 2 * A_T;
        const __nv_bfloat16* B1 = st + 2 * A_T + B_T;

        #pragma unroll
        for (int ks = 0; ks < 2; ks++) {
            wmma::fragment<wmma::matrix_b, 16, 16, 16, __nv_bfloat16, wmma::row_major> bh[4];
            wmma::fragment<wmma::matrix_a, 16, 16, 16, __nv_bfloat16, wmma::row_major> ah[4];
            #pragma unroll
            for (int ni = 0; ni < 4; ni++)
                wmma::load_matrix_sync(bh[ni],
                    &B0[(ks * 16) * LDB + wn * 64 + ni * 16], LDB);
            #pragma unroll
            for (int mi = 0; mi < 4; mi++)
                wmma::load_matrix_sync(ah[mi],
                    &A0[(wm * 64 + mi * 16) * LDA + ks * 16], LDA);
            #pragma unroll
            for (int mi = 0; mi < 4; mi++)
                #pragma unroll
                for (int ni = 0; ni < 4; ni++)
                    wmma::mma_sync(acc[mi][ni], ah[mi], bh[ni], acc[mi][ni]);
            {
                wmma::fragment<wmma::matrix_a, 16, 16, 16, __nv_bfloat16, wmma::row_major> al[4];
                #pragma unroll
                for (int mi = 0; mi < 4; mi++)
                    wmma::load_matrix_sync(al[mi],
                        &A1[(wm * 64 + mi * 16) * LDA + ks * 16], LDA);
                #pragma unroll
                for (int mi = 0; mi < 4; mi++)
                    #pragma unroll
                    for (int ni = 0; ni < 4; ni++)
                        wmma::mma_sync(acc[mi][ni], al[mi], bh[ni], acc[mi][ni]);
            }
            {
                wmma::fragment<wmma::matrix_b, 16, 16, 16, __nv_bfloat16, wmma::row_major> bl[4];
                #pragma unroll
                for (int ni = 0; ni < 4; ni++)
                    wmma::load_matrix_sync(bl[ni],
                        &B1[(ks * 16) * LDB + wn * 64 + ni * 16], LDB);
                #pragma unroll
                for (int mi = 0; mi < 4; mi++)
                    #pragma unroll
                    for (int ni = 0; ni < 4; ni++)
                        wmma::mma_sync(acc[mi][ni], ah[mi], bl[ni], acc[mi][ni]);
            }
        }
    }
    CP_WAIT0();
    __syncthreads();

    float* Cb = C + (size_t)batch * Mtotal * 4096;
    #pragma unroll
    for (int mi = 0; mi < 4; mi++)
        #pragma unroll
        for (int ni = 0; ni < 4; ni++)
            wmma::store_matrix_sync(
                Cb + (size_t)(bm + wm * 64 + mi * 16) * 4096 + n0 + wn * 64 + ni * 16,
                acc[mi][ni], 4096, wmma::mem_row_major);
}

// ---------------- vectorized split fp32 -> bf16 hi/lo (x only) ---------------
__device__ __forceinline__ uint32_t pack2(float a, float b) {
    __nv_bfloat162 t = __floats2bfloat162_rn(a, b);
    return *reinterpret_cast<uint32_t*>(&t);
}
__global__ void split4_kernel(const float4* __restrict__ in,
                              uint2* __restrict__ hi,
                              uint2* __restrict__ lo, int n4)
{
    int i = blockIdx.x * 256 + threadIdx.x;
    if (i < n4) {
        float4 v = in[i];
        float h0 = __bfloat162float(__float2bfloat16(v.x));
        float h1 = __bfloat162float(__float2bfloat16(v.y));
        float h2 = __bfloat162float(__float2bfloat16(v.z));
        float h3 = __bfloat162float(__float2bfloat16(v.w));
        hi[i] = make_uint2(pack2(h0, h1), pack2(h2, h3));
        lo[i] = make_uint2(pack2(v.x - h0, v.y - h1), pack2(v.z - h2, v.w - h3));
    }
}

// ------- fp32 fold GEMM, epilogue writes bf16 hi/lo directly -----------------
__global__ void __launch_bounds__(256) sgemm_fold(
    const float* __restrict__ A, const float* __restrict__ Bm,
    __nv_bfloat16* __restrict__ Hi, __nv_bfloat16* __restrict__ Lo,
    int M, int N, int K)
{
    constexpr int BM = 128, BN = 128, BK = 16;
    __shared__ float As[2][BK][BM];
    __shared__ float Bs[2][BK][BN];

    const int bm = blockIdx.y * BM;
    const int bn = blockIdx.x * BN;
    const int tid = threadIdx.x;
    const int tx = tid & 15;
    const int ty = tid >> 4;

    const int arow = tid >> 2;
    const int ac4  = (tid & 3) * 4;
    const int brow = tid >> 5;
    const int bc4  = (tid & 31) * 4;

    float4 ra0, ra1, rb0, rb1;
    ra0 = *reinterpret_cast<const float4*>(A + (size_t)(bm + arow) * K + ac4);
    ra1 = *reinterpret_cast<const float4*>(A + (size_t)(bm + arow + 64) * K + ac4);
    rb0 = *reinterpret_cast<const float4*>(Bm + (size_t)(brow) * N + bn + bc4);
    rb1 = *reinterpret_cast<const float4*>(Bm + (size_t)(brow + 8) * N + bn + bc4);
    As[0][ac4 + 0][arow] = ra0.x; As[0][ac4 + 1][arow] = ra0.y;
    As[0][ac4 + 2][arow] = ra0.z; As[0][ac4 + 3][arow] = ra0.w;
    As[0][ac4 + 0][arow + 64] = ra1.x; As[0][ac4 + 1][arow + 64] = ra1.y;
    As[0][ac4 + 2][arow + 64] = ra1.z; As[0][ac4 + 3][arow + 64] = ra1.w;
    *reinterpret_cast<float4*>(&Bs[0][brow][bc4]) = rb0;
    *reinterpret_cast<float4*>(&Bs[0][brow + 8][bc4]) = rb1;
    __syncthreads();

    float acc[8][8] = {};
    int buf = 0;
    for (int k0 = 0; k0 < K; k0 += BK) {
        const bool more = (k0 + BK) < K;
        if (more) {
            int kn = k0 + BK;
            ra0 = *reinterpret_cast<const float4*>(A + (size_t)(bm + arow) * K + kn + ac4);
            ra1 = *reinterpret_cast<const float4*>(A + (size_t)(bm + arow + 64) * K + kn + ac4);
            rb0 = *reinterpret_cast<const float4*>(Bm + (size_t)(kn + brow) * N + bn + bc4);
            rb1 = *reinterpret_cast<const float4*>(Bm + (size_t)(kn + brow + 8) * N + bn + bc4);
        }
        #pragma unroll
        for (int kk = 0; kk < BK; kk++) {
            float4 a0 = *reinterpret_cast<const float4*>(&As[buf][kk][ty * 8]);
            float4 a1 = *reinterpret_cast<const float4*>(&As[buf][kk][ty * 8 + 4]);
            float4 b0 = *reinterpret_cast<const float4*>(&Bs[buf][kk][tx * 8]);
            float4 b1 = *reinterpret_cast<const float4*>(&Bs[buf][kk][tx * 8 + 4]);
            float ar[8] = {a0.x, a0.y, a0.z, a0.w, a1.x, a1.y, a1.z, a1.w};
            float br[8] = {b0.x, b0.y, b0.z, b0.w, b1.x, b1.y, b1.z, b1.w};
            #pragma unroll
            for (int i = 0; i < 8; i++)
                #pragma unroll
                for (int j = 0; j < 8; j++)
                    acc[i][j] = fmaf(ar[i], br[j], acc[i][j]);
        }
        if (more) {
            int nb = buf ^ 1;
            As[nb][ac4 + 0][arow] = ra0.x; As[nb][ac4 + 1][arow] = ra0.y;
            As[nb][ac4 + 2][arow] = ra0.z; As[nb][ac4 + 3][arow] = ra0.w;
            As[nb][ac4 + 0][arow + 64] = ra1.x; As[nb][ac4 + 1][arow + 64] = ra1.y;
            As[nb][ac4 + 2][arow + 64] = ra1.z; As[nb][ac4 + 3][arow + 64] = ra1.w;
            *reinterpret_cast<float4*>(&Bs[nb][brow][bc4]) = rb0;
            *reinterpret_cast<float4*>(&Bs[nb][brow + 8][bc4]) = rb1;
            __syncthreads();
            buf = nb;
        }
    }
    #pragma unroll
    for (int i = 0; i < 8; i++) {
        int m = bm + ty * 8 + i;
        #pragma unroll
        for (int j = 0; j < 8; j++) {
            float v = acc[i][j];
            __nv_bfloat16 h = __float2bfloat16(v);
            Hi[(size_t)m * N + bn + tx * 8 + j] = h;
            Lo[(size_t)m * N + bn + tx * 8 + j] =
                __float2bfloat16(v - __bfloat162float(h));
        }
    }
}

// ---------------- fold biases -----------------------------------------------
__global__ void fold_bias(const float* __restrict__ wqkv,
                          const float* __restrict__ wg1,
                          const float* __restrict__ bg1,
                          const float* __restrict__ b0)
{
    int i = blockIdx.x * 256 + threadIdx.x;
    if (i < 1536) {
        float s = 0.f;
        for (int k = 0; k < 512; k++) s = fmaf(wqkv[(size_t)i * 512 + k], b0[k], s);
        g_bqkv[i] = s;
    } else if (i < 1536 + 256) {
        int j = i - 1536;
        float s = bg1[j];
        for (int k = 0; k < 512; k++) s = fmaf(wg1[(size_t)j * 512 + k], b0[k], s);
        g_bg1[j] = s;
    }
}

// ------- depthwise 3x3 SAME, bias fused at load, sumsq reduction fused ------
__global__ void __launch_bounds__(256) dwconv_kernel(
    const float* __restrict__ inp, const float* __restrict__ w,
    const float* __restrict__ bias, float* __restrict__ outp)
{
    const int bc = blockIdx.x;
    const int ch = bc % 1536;
    const float* ip = inp + (size_t)bc * 4096;
    float*       op = outp + (size_t)bc * 4096;
    __shared__ float sh[66 * 66];
    __shared__ float red[256];
    const int tid = threadIdx.x;
    const float bv = bias[ch];
    for (int i = tid; i < 66 * 66; i += 256) {
        int r = i / 66 - 1;
        int c = i % 66 - 1;
        sh[i] = (r >= 0 && r < 64 && c >= 0 && c < 64) ? ip[r * 64 + c] + bv : 0.f;
    }
    const float* wp = w + (size_t)ch * 9;
    float w0 = wp[0], w1 = wp[1], w2 = wp[2];
    float w3 = wp[3], w4 = wp[4], w5 = wp[5];
    float w6 = wp[6], w7 = wp[7], w8 = wp[8];
    __syncthreads();
    float ss = 0.f;
    #pragma unroll
    for (int j = 0; j < 16; j++) {
        int p = tid + j * 256;
        int y = p >> 6, x = p & 63;
        const float* s0 = &sh[y * 66 + x];
        float o = s0[0]   * w0 + s0[1]   * w1 + s0[2]   * w2
                + s0[66]  * w3 + s0[67]  * w4 + s0[68]  * w5
                + s0[132] * w6 + s0[133] * w7 + s0[134] * w8;
        op[p] = o;
        ss = fmaf(o, o, ss);
    }
    red[tid] = ss;
    __syncthreads();
    for (int st = 128; st > 0; st >>= 1) {
        if (tid < st) red[tid] += red[tid + st];
        __syncthreads();
    }
    if (tid == 0) g_ss[bc] = red[0];
}

// ---------------- inverse norms from fused sumsq -----------------------------
__global__ void inv_norm()
{
    int i = blockIdx.x * 256 + threadIdx.x;   // 0..8191
    if (i < 8192) {
        int qk = i >> 12;
        int rr = i & 4095;
        int b = rr >> 9, hc = rr & 511;
        float ss = g_ss[b * 1536 + qk * 512 + hc];
        float inv = 1.f / fmaxf(sqrtf(ss), 1e-12f);
        (qk ? g_kinv : g_qinv)[rr] = inv;
    }
}

// ---------------- gate: bias+relu fused, sigmoid dot, partial sums ----------
__global__ void __launch_bounds__(256) gate_dot(
    const float* __restrict__ g1, const float* __restrict__ wg2,
    const float* __restrict__ bg1f, const float* __restrict__ bg2)
{
    __shared__ float ws[256];
    __shared__ float bs[256];
    __shared__ float red[256];
    const int tid = threadIdx.x;
    ws[tid] = wg2[tid];
    bs[tid] = bg1f[tid];
    __syncthreads();
    const int P = blockIdx.x * 256 + tid;
    const int b = P >> 12;
    const int p = P & 4095;
    const float* base = g1 + (size_t)b * 256 * 4096 + p;
    float acc = bg2[0];
    #pragma unroll 8
    for (int ch = 0; ch < 256; ch++)
        acc = fmaf(fmaxf(base[(size_t)ch * 4096] + bs[ch], 0.f), ws[ch], acc);
    float s = 1.f / (1.f + expf(-acc));
    red[tid] = s;
    __syncthreads();
    for (int st = 128; st > 0; st >>= 1) {
        if (tid < st) red[tid] += red[tid + st];
        __syncthreads();
    }
    if (tid == 0) g_partial[blockIdx.x] = red[0];
}

__global__ void gate_fin()
{
    if (threadIdx.x == 0 && blockIdx.x == 0) {
        float t = 0.f;
        for (int i = 0; i < 128; i++) t += g_partial[i];
        float mean = t * (1.f / 32768.f);
        int k = (int)floorf(64.f * mean);
        g_dk = max(0, min(64, k));
    }
}

// ---------------- split-K QK^T partials --------------------------------------
__global__ void __launch_bounds__(256) qk_gemm(const float* __restrict__ qkv)
{
    __shared__ float Qt[64 * 68];
    __shared__ float Kt[64 * 68];

    const int bh = blockIdx.y;
    const int b = bh >> 3, h = bh & 7;
    const float* Qg = qkv + ((size_t)b * 1536 + (size_t)h * 64) * 4096;
    const float* Kg = Qg + (size_t)512 * 4096;
    const int n_base = blockIdx.x * 512;

    const int tid = threadIdx.x;
    const int tx = tid & 15, ty = tid >> 4;

    float acc[4][4] = {};
    for (int n0 = n_base; n0 < n_base + 512; n0 += 64) {
        #pragma unroll
        for (int l = 0; l < 4; l++) {
            int f   = tid + l * 256;
            int row = f >> 4;
            int nl  = (f & 15) * 4;
            float4 q4 = *reinterpret_cast<const float4*>(Qg + (size_t)row * 4096 + n0 + nl);
            float4 k4 = *reinterpret_cast<const float4*>(Kg + (size_t)row * 4096 + n0 + nl);
            Qt[(nl + 0) * 68 + row] = q4.x; Qt[(nl + 1) * 68 + row] = q4.y;
            Qt[(nl + 2) * 68 + row] = q4.z; Qt[(nl + 3) * 68 + row] = q4.w;
            Kt[(nl + 0) * 68 + row] = k4.x; Kt[(nl + 1) * 68 + row] = k4.y;
            Kt[(nl + 2) * 68 + row] = k4.z; Kt[(nl + 3) * 68 + row] = k4.w;
        }
        __syncthreads();
        #pragma unroll 8
        for (int nn = 0; nn < 64; nn++) {
            float4 av = *reinterpret_cast<const float4*>(&Qt[nn * 68 + ty * 4]);
            float4 bv = *reinterpret_cast<const float4*>(&Kt[nn * 68 + tx * 4]);
            float ar[4] = {av.x, av.y, av.z, av.w};
            float br[4] = {bv.x, bv.y, bv.z, bv.w};
            #pragma unroll
            for (int i = 0; i < 4; i++)
                #pragma unroll
                for (int j = 0; j < 4; j++)
                    acc[i][j] = fmaf(ar[i], br[j], acc[i][j]);
        }
        __syncthreads();
    }
    float* Sp = &g_Spart[((size_t)blockIdx.x * 64 + bh) * 4096];
    #pragma unroll
    for (int i = 0; i < 4; i++) {
        float4 v;
        v.x = acc[i][0]; v.y = acc[i][1]; v.z = acc[i][2]; v.w = acc[i][3];
        *reinterpret_cast<float4*>(&Sp[(ty * 4 + i) * 64 + tx * 4]) = v;
    }
}

// ---------------- reduce + scale + top-k + softmax ---------------------------
__global__ void __launch_bounds__(256) topk_softmax(const float* __restrict__ temp)
{
    __shared__ float S[64 * 65];
    const int bh = blockIdx.x;
    const int b = bh >> 3, h = bh & 7;
    const int tid = threadIdx.x;
    const int base = b * 512 + h * 64;
    const float tmp = temp[h];

    for (int e = tid; e < 4096; e += 256) {
        float s = 0.f;
        #pragma unroll
        for (int c = 0; c < 8; c++)
            s += g_Spart[((size_t)c * 64 + bh) * 4096 + e];
        int row = e >> 6, col = e & 63;
        S[row * 65 + col] = s * g_qinv[base + row] * tmp * g_kinv[base + col];
    }
    __syncthreads();

    const int kd = g_dk;
    if (tid < 64) {
        float* row = &S[tid * 65];
        float m = -INFINITY;
        unsigned long long keep = 0ull;
        for (int i = 0; i < 64; i++) {
            float ai = row[i];
            int cnt = 0;
            for (int j = 0; j < 64; j++) {
                float aj = row[j];
                cnt += (aj > ai) ? 1 : ((aj == ai && j < i) ? 1 : 0);
            }
            if (cnt < kd) { keep |= (1ull << i); m = fmaxf(m, ai); }
        }
        float s = 0.f;
        for (int i = 0; i < 64; i++) {
            float e = ((keep >> i) & 1ull) ? expf(row[i] - m) : 0.f;
            row[i] = e;
            s += e;
        }
        float inv = (s > 0.f) ? 1.f / s : 0.f;
        for (int i = 0; i < 64; i++) row[i] *= inv;
    }
    __syncthreads();
    for (int e = tid; e < 4096; e += 256) {
        int row = e >> 6, col = e & 63;
        g_P[(size_t)bh * 4096 + e] = S[row * 65 + col];
    }
}

// ---------------- out = sc * P @ V -------------------------------------------
__global__ void __launch_bounds__(256) av_gemm(
    const float* __restrict__ qkv,
    const float* __restrict__ a1p, const float* __restrict__ a2p,
    const float* __restrict__ a3p, const float* __restrict__ a4p,
    float* __restrict__ outp)
{
    __shared__ float P[64 * 65];
    __shared__ float Vt[64 * 68];

    const int bh = blockIdx.y;
    const int b = bh >> 3, h = bh & 7;
    const float* Vg = qkv + ((size_t)b * 1536 + 1024 + (size_t)h * 64) * 4096;
    float* Og = outp + ((size_t)b * 512 + (size_t)h * 64) * 4096;
    const int n_base = blockIdx.x * 512;
    const float sc = a1p[0] + a2p[0] + a3p[0] + a4p[0];

    const int tid = threadIdx.x;
    const int tx = tid & 15, ty = tid >> 4;

    for (int e = tid; e < 4096; e += 256) {
        int row = e >> 6, col = e & 63;
        P[row * 65 + col] = g_P[(size_t)bh * 4096 + e];
    }
    __syncthreads();

    for (int n0 = n_base; n0 < n_base + 512; n0 += 64) {
        #pragma unroll
        for (int l = 0; l < 4; l++) {
            int f   = tid + l * 256;
            int row = f >> 4;
            int nl  = (f & 15) * 4;
            *reinterpret_cast<float4*>(&Vt[row * 68 + nl]) =
                *reinterpret_cast<const float4*>(Vg + (size_t)row * 4096 + n0 + nl);
        }
        __syncthreads();
        float o[4][4] = {};
        #pragma unroll 4
        for (int d = 0; d < 64; d++) {
            float s0 = P[(ty * 4 + 0) * 65 + d];
            float s1 = P[(ty * 4 + 1) * 65 + d];
            float s2 = P[(ty * 4 + 2) * 65 + d];
            float s3 = P[(ty * 4 + 3) * 65 + d];
            float4 v4 = *reinterpret_cast<const float4*>(&Vt[d * 68 + tx * 4]);
            o[0][0] = fmaf(s0, v4.x, o[0][0]); o[0][1] = fmaf(s0, v4.y, o[0][1]);
            o[0][2] = fmaf(s0, v4.z, o[0][2]); o[0][3] = fmaf(s0, v4.w, o[0][3]);
            o[1][0] = fmaf(s1, v4.x, o[1][0]); o[1][1] = fmaf(s1, v4.y, o[1][1]);
            o[1][2] = fmaf(s1, v4.z, o[1][2]); o[1][3] = fmaf(s1, v4.w, o[1][3]);
            o[2][0] = fmaf(s2, v4.x, o[2][0]); o[2][1] = fmaf(s2, v4.y, o[2][1]);
            o[2][2] = fmaf(s2, v4.z, o[2][2]); o[2][3] = fmaf(s2, v4.w, o[2][3]);
            o[3][0] = fmaf(s3, v4.x, o[3][0]); o[3][1] = fmaf(s3, v4.y, o[3][1]);
            o[3][2] = fmaf(s3, v4.z, o[3][2]); o[3][3] = fmaf(s3, v4.w, o[3][3]);
        }
        #pragma unroll
        for (int i = 0; i < 4; i++) {
            float4 w;
            w.x = o[i][0] * sc; w.y = o[i][1] * sc;
            w.z = o[i][2] * sc; w.w = o[i][3] * sc;
            *reinterpret_cast<float4*>(Og + (size_t)(ty * 4 + i) * 4096 + n0 + tx * 4) = w;
        }
        __syncthreads();
    }
}

// ---------------------------------------------------------------------------
extern "C" void kernel_launch(void* const* d_in, const int* in_sizes, int n_in,
                              void* d_out, int out_size)
{
    const float* x    = (const float*)d_in[0];
    const float* w0   = (const float*)d_in[1];
    const float* b0   = (const float*)d_in[2];
    const float* wqkv = (const float*)d_in[3];
    const float* wdw  = (const float*)d_in[4];
    const float* temp = (const float*)d_in[5];
    const float* wg1  = (const float*)d_in[6];
    const float* bg1  = (const float*)d_in[7];
    const float* wg2  = (const float*)d_in[8];
    const float* bg2  = (const float*)d_in[9];
    const float* a1   = (const float*)d_in[10];
    const float* a2   = (const float*)d_in[11];
    const float* a3   = (const float*)d_in[12];
    const float* a4   = (const float*)d_in[13];
    float* out = (float*)d_out;

    float *bqkv, *bg1f, *qkvp, *qkvb, *g1;
    __nv_bfloat16 *Wqh, *Wql, *Wgh, *Wgl, *Xh, *Xl;
    cudaGetSymbolAddress((void**)&bqkv, g_bqkv);
    cudaGetSymbolAddress((void**)&bg1f, g_bg1);
    cudaGetSymbolAddress((void**)&qkvp, g_qkvp);
    cudaGetSymbolAddress((void**)&qkvb, g_qkv);
    cudaGetSymbolAddress((void**)&g1,   g_g1);
    cudaGetSymbolAddress((void**)&Wqh,  g_Wqkv_hi);
    cudaGetSymbolAddress((void**)&Wql,  g_Wqkv_lo);
    cudaGetSymbolAddress((void**)&Wgh,  g_Wg1_hi);
    cudaGetSymbolAddress((void**)&Wgl,  g_Wg1_lo);
    cudaGetSymbolAddress((void**)&Xh,   g_Xhi);
    cudaGetSymbolAddress((void**)&Xl,   g_Xlo);

    cudaFuncSetAttribute(mma_gemm, cudaFuncAttributeMaxDynamicSharedMemorySize, GEMM_SMEM);

    // streams/events created once (resources only; work is identical per call)
    static cudaStream_t s1 = nullptr, s2 = nullptr;
    static cudaEvent_t evRoot, evB, evDW, evGATE, evINV;
    if (s1 == nullptr) {
        cudaStreamCreateWithFlags(&s1, cudaStreamNonBlocking);
        cudaStreamCreateWithFlags(&s2, cudaStreamNonBlocking);
        cudaEventCreateWithFlags(&evRoot, cudaEventDisableTiming);
        cudaEventCreateWithFlags(&evB,    cudaEventDisableTiming);
        cudaEventCreateWithFlags(&evDW,   cudaEventDisableTiming);
        cudaEventCreateWithFlags(&evGATE, cudaEventDisableTiming);
        cudaEventCreateWithFlags(&evINV,  cudaEventDisableTiming);
    }

    dim3 blk(256);

    // fork s1/s2 off the capture stream
    cudaEventRecord(evRoot, 0);
    cudaStreamWaitEvent(s1, evRoot, 0);
    cudaStreamWaitEvent(s2, evRoot, 0);

    // s0: x split
    split4_kernel<<<16384, blk>>>((const float4*)x, (uint2*)Xh, (uint2*)Xl, 4194304);

    // s1: qkv weight fold (writes hi/lo directly) + bias folds
    sgemm_fold<<<dim3(4, 12), blk, 0, s1>>>(wqkv, w0, Wqh, Wql, 1536, 512, 512);
    fold_bias<<<8, blk, 0, s1>>>(wqkv, wg1, bg1, b0);
    cudaEventRecord(evB, s1);

    // s2: gate weight fold, then gate pipeline (overlaps dwconv on s0)
    sgemm_fold<<<dim3(4, 2), blk, 0, s2>>>(wg1, w0, Wgh, Wgl, 256, 512, 512);
    cudaEventRecord(evRoot, 0);  // x split done marker on s0
    cudaStreamWaitEvent(s2, evRoot, 0);
    mma_gemm<<<dim3(16, 2, 8), blk, GEMM_SMEM, s2>>>(Wgh, Wgl, Xh, Xl, g1, 256);
    cudaStreamWaitEvent(s2, evB, 0);
    gate_dot<<<128, blk, 0, s2>>>(g1, wg2, bg1f, bg2);
    gate_fin<<<1, 32, 0, s2>>>();
    cudaEventRecord(evGATE, s2);

    // s0: qkv GEMM -> dwconv -> qk
    cudaStreamWaitEvent(0, evB, 0);
    mma_gemm<<<dim3(16, 12, 8), blk, GEMM_SMEM>>>(Wqh, Wql, Xh, Xl, qkvp, 1536);
    dwconv_kernel<<<8 * 1536, blk>>>(qkvp, wdw, bqkv, qkvb);
    cudaEventRecord(evDW, 0);
    qk_gemm<<<dim3(8, 64), blk>>>(qkvb);

    // s1: inv_norm overlaps qk_gemm
    cudaStreamWaitEvent(s1, evDW, 0);
    inv_norm<<<32, blk, 0, s1>>>();
    cudaEventRecord(evINV, s1);

    // s0: join and finish
    cudaStreamWaitEvent(0, evGATE, 0);
    cudaStreamWaitEvent(0, evINV, 0);
    topk_softmax<<<64, blk>>>(temp);
    av_gemm<<<dim3(8, 64), blk>>>(qkvb, a1, a2, a3, a4, out);
}